// round 14
// baseline (speedup 1.0000x reference)
#include <cuda_runtime.h>
#include <cuda_bf16.h>
#include <cuda_fp16.h>
#include <math.h>
#include <stdint.h>

#define BT   18464          // B*T
#define B_   32
#define T_   577
#define D_   768
#define H_   3072
#define NH   12
#define KPAD 584            // padded key dim for dp/probs rows (16B-aligned)
#define PTT  (T_ * KPAD)    // per-(b,h) plane size (divisible by 4)

// ---------------- static scratch ----------------
__device__ __nv_bfloat16 g_y_hi [(size_t)BT * D_];
__device__ __nv_bfloat16 g_y_lo [(size_t)BT * D_];
__device__ __nv_bfloat16 g_qkv_hi[(size_t)BT * 2304];  // V cols [1536,2304) hold fp16 bits
__device__ __nv_bfloat16 g_qkv_lo[(size_t)BT * 2304];
__device__ float         g_dp   [(size_t)B_ * NH * PTT];
__device__ __half        g_p    [(size_t)B_ * NH * PTT];
__device__ __nv_bfloat16 g_wa_hi[(size_t)BT * D_];
__device__ __nv_bfloat16 g_wa_lo[(size_t)BT * D_];
__device__ float         g_x1   [(size_t)BT * D_];
__device__ __nv_bfloat16 g_h_hi [(size_t)BT * H_];
__device__ __nv_bfloat16 g_h_lo [(size_t)BT * H_];
__device__ __nv_bfloat16 g_wq_hi[2304 * 768], g_wq_lo[2304 * 768];
__device__ __nv_bfloat16 g_wp_hi[ 768 * 768], g_wp_lo[ 768 * 768];
__device__ __nv_bfloat16 g_w1_hi[3072 * 768], g_w1_lo[3072 * 768];
__device__ __nv_bfloat16 g_w2_hi[ 768 * 3072], g_w2_lo[ 768 * 3072];

// ---------------- helpers ----------------
__device__ __forceinline__ uint32_t smem_u32(const void* p) {
    uint32_t a;
    asm("{ .reg .u64 t; cvta.to.shared.u64 t, %1; cvt.u32.u64 %0, t; }" : "=r"(a) : "l"(p));
    return a;
}
__device__ __forceinline__ void cp16(uint32_t dst, const void* src) {
    asm volatile("cp.async.cg.shared.global [%0], [%1], 16;" :: "r"(dst), "l"(src));
}
__device__ __forceinline__ void cp16z(uint32_t dst, const void* src, int nb) {
    asm volatile("cp.async.cg.shared.global [%0], [%1], 16, %2;" :: "r"(dst), "l"(src), "r"(nb));
}
#define CP_COMMIT() asm volatile("cp.async.commit_group;" ::: "memory")
#define CP_WAIT(n)  asm volatile("cp.async.wait_group %0;" :: "n"(n) : "memory")

__device__ __forceinline__ void ldsm4(uint32_t* r, uint32_t a) {
    asm volatile("ldmatrix.sync.aligned.m8n8.x4.shared.b16 {%0,%1,%2,%3}, [%4];"
                 : "=r"(r[0]), "=r"(r[1]), "=r"(r[2]), "=r"(r[3]) : "r"(a));
}
__device__ __forceinline__ void ldsm4t(uint32_t* r, uint32_t a) {
    asm volatile("ldmatrix.sync.aligned.m8n8.x4.trans.shared.b16 {%0,%1,%2,%3}, [%4];"
                 : "=r"(r[0]), "=r"(r[1]), "=r"(r[2]), "=r"(r[3]) : "r"(a));
}
__device__ __forceinline__ void mma16816(float* c, const uint32_t* a, uint32_t b0, uint32_t b1) {
    asm volatile("mma.sync.aligned.m16n8k16.row.col.f32.bf16.bf16.f32 "
                 "{%0,%1,%2,%3}, {%4,%5,%6,%7}, {%8,%9}, {%0,%1,%2,%3};"
                 : "+f"(c[0]), "+f"(c[1]), "+f"(c[2]), "+f"(c[3])
                 : "r"(a[0]), "r"(a[1]), "r"(a[2]), "r"(a[3]), "r"(b0), "r"(b1));
}
__device__ __forceinline__ void mma16816h(float* c, const uint32_t* a, uint32_t b0, uint32_t b1) {
    asm volatile("mma.sync.aligned.m16n8k16.row.col.f32.f16.f16.f32 "
                 "{%0,%1,%2,%3}, {%4,%5,%6,%7}, {%8,%9}, {%0,%1,%2,%3};"
                 : "+f"(c[0]), "+f"(c[1]), "+f"(c[2]), "+f"(c[3])
                 : "r"(a[0]), "r"(a[1]), "r"(a[2]), "r"(a[3]), "r"(b0), "r"(b1));
}

// ---------------- weight transpose+split ----------------
__global__ void wconv_kernel(const float* __restrict__ W,
                             __nv_bfloat16* __restrict__ hi,
                             __nv_bfloat16* __restrict__ lo, int K, int N) {
    __shared__ float t[32][33];
    const int k0 = blockIdx.y * 32, n0 = blockIdx.x * 32;
    #pragma unroll
    for (int i = 0; i < 4; i++)
        t[threadIdx.y + i * 8][threadIdx.x] =
            W[(size_t)(k0 + threadIdx.y + i * 8) * N + n0 + threadIdx.x];
    __syncthreads();
    #pragma unroll
    for (int i = 0; i < 4; i++) {
        int n = n0 + threadIdx.y + i * 8;
        int k = k0 + threadIdx.x;
        float x = t[threadIdx.x][threadIdx.y + i * 8];
        __nv_bfloat16 h = __float2bfloat16(x);
        hi[(size_t)n * K + k] = h;
        lo[(size_t)n * K + k] = __float2bfloat16(x - __bfloat162float(h));
    }
}

// ---------------- LayerNorm -> split bf16 ----------------
__global__ void __launch_bounds__(256) ln_kernel(const float* __restrict__ x,
                                                 const float* __restrict__ w,
                                                 const float* __restrict__ b,
                                                 __nv_bfloat16* __restrict__ yhi,
                                                 __nv_bfloat16* __restrict__ ylo) {
    const int row = blockIdx.x;
    const float* xr = x + (size_t)row * D_;
    const int tid = threadIdx.x;

    float v0 = xr[tid], v1 = xr[tid + 256], v2 = xr[tid + 512];
    float s  = v0 + v1 + v2;
    float s2 = v0 * v0 + v1 * v1 + v2 * v2;
    #pragma unroll
    for (int o = 16; o > 0; o >>= 1) {
        s  += __shfl_xor_sync(0xffffffffu, s,  o);
        s2 += __shfl_xor_sync(0xffffffffu, s2, o);
    }
    __shared__ float sh[8], sh2[8];
    const int wi = tid >> 5, ln = tid & 31;
    if (ln == 0) { sh[wi] = s; sh2[wi] = s2; }
    __syncthreads();
    if (wi == 0) {
        s  = (ln < 8) ? sh[ln]  : 0.f;
        s2 = (ln < 8) ? sh2[ln] : 0.f;
        #pragma unroll
        for (int o = 4; o > 0; o >>= 1) {
            s  += __shfl_xor_sync(0xffffffffu, s,  o);
            s2 += __shfl_xor_sync(0xffffffffu, s2, o);
        }
        if (ln == 0) { sh[0] = s; sh2[0] = s2; }
    }
    __syncthreads();
    const float mu  = sh[0] * (1.0f / D_);
    const float var = sh2[0] * (1.0f / D_) - mu * mu;
    const float rs  = rsqrtf(var + 1e-6f);
    size_t base = (size_t)row * D_;
    #pragma unroll
    for (int j = 0; j < 3; j++) {
        int c = tid + j * 256;
        float v = (j == 0 ? v0 : (j == 1 ? v1 : v2));
        float y = (v - mu) * rs * w[c] + b[c];
        __nv_bfloat16 h = __float2bfloat16(y);
        yhi[base + c] = h;
        ylo[base + c] = __float2bfloat16(y - __bfloat162float(h));
    }
}

// ================= linear GEMM: 128x128 CTA, 8 warps 32x64, BK=32, 3-stage swizzled, occ=2 =================
// 64B rows, XOR swizzle seg' = seg ^ ((row>>1)&3) -> ldmatrix conflict-free, stage 32KB.
// Single __syncthreads per chunk (3-stage removes the WAR sync).
#define STG3 32768u
template <int ACT, bool RES, bool OSPLIT>
__global__ void __launch_bounds__(256, 2) gemm_lin(
    const __nv_bfloat16* __restrict__ Ahi, const __nv_bfloat16* __restrict__ Alo,
    const __nv_bfloat16* __restrict__ Whi, const __nv_bfloat16* __restrict__ Wlo,
    const float* __restrict__ bias, const float* __restrict__ res,
    float* __restrict__ C, __nv_bfloat16* __restrict__ Chi, __nv_bfloat16* __restrict__ Clo,
    int M, int N, int K, int vstart) {
    extern __shared__ __align__(128) char dsm[];
    const uint32_t sb = smem_u32(dsm);
    const int tid = threadIdx.x;
    const int lane = tid & 31, wid = tid >> 5;
    const int m0 = blockIdx.y * 128, n0 = blockIdx.x * 128;
    const int wm = (wid & 3) * 32, wn = (wid >> 2) * 64;
    const int lrow = tid >> 2;          // 0..63
    const int lseg = tid & 3;           // 16B segment in row
    const int mi = lane >> 3, r8 = lane & 7;
    const uint32_t xr_ = (uint32_t)((r8 >> 1) & 3);   // ldsm lane swizzle
    const int a_row = wm + (mi & 1) * 8 + r8;
    const int b_row = wn + (mi >> 1) * 8 + r8;
    const uint32_t aoff = (uint32_t)(a_row * 64) + ((((uint32_t)(mi >> 1)) ^ xr_) << 4);
    const uint32_t boff = (uint32_t)(b_row * 64) + ((((uint32_t)(mi & 1)) ^ xr_) << 4);

    float acc[2][8][4];
    #pragma unroll
    for (int a = 0; a < 2; a++)
        #pragma unroll
        for (int b = 0; b < 8; b++)
            #pragma unroll
            for (int d = 0; d < 4; d++) acc[a][b][d] = 0.f;

    const int nc = K >> 5;

    auto load_chunk = [&](int c) {
        const uint32_t st = sb + (uint32_t)(c % 3) * STG3;
        const int k0 = c << 5;
        #pragma unroll
        for (int i = 0; i < 2; i++) {
            int r = lrow + i * 64;
            uint32_t dseg = (uint32_t)lseg ^ (uint32_t)((r >> 1) & 3);
            uint32_t d = st + (uint32_t)(r * 64) + (dseg << 4);
            int gr = m0 + r; if (gr > M - 1) gr = M - 1;
            const char* srcA = (const char*)(Ahi + (size_t)gr * K + k0) + lseg * 16;
            const char* srcAl = (const char*)(Alo + (size_t)gr * K + k0) + lseg * 16;
            size_t gb = (size_t)(n0 + r) * K + k0;
            cp16(d,          srcA);
            cp16(d + 8192u,  srcAl);
            cp16(d + 16384u, (const char*)(Whi + gb) + lseg * 16);
            cp16(d + 24576u, (const char*)(Wlo + gb) + lseg * 16);
        }
    };

    load_chunk(0); CP_COMMIT();
    if (nc > 1) load_chunk(1);
    CP_COMMIT();

    for (int c = 0; c < nc; c++) {
        CP_WAIT(1);
        __syncthreads();
        if (c + 2 < nc) load_chunk(c + 2);
        CP_COMMIT();
        const uint32_t st = sb + (uint32_t)(c % 3) * STG3;
        #pragma unroll
        for (int kb = 0; kb < 2; kb++) {
            const uint32_t kx = (uint32_t)(kb * 32);  // seg+2 == XOR bit5
            uint32_t ah[2][4], al[2][4];
            ldsm4(ah[0], (st + aoff) ^ kx);
            ldsm4(ah[1], (st + aoff + 1024u) ^ kx);
            ldsm4(al[0], (st + 8192u + aoff) ^ kx);
            ldsm4(al[1], (st + 8192u + aoff + 1024u) ^ kx);
            #pragma unroll
            for (int p = 0; p < 4; p++) {
                uint32_t bh[4], bl[4];
                ldsm4(bh, (st + 16384u + boff + (uint32_t)(p * 1024)) ^ kx);
                ldsm4(bl, (st + 24576u + boff + (uint32_t)(p * 1024)) ^ kx);
                #pragma unroll
                for (int mt = 0; mt < 2; mt++) {
                    mma16816(acc[mt][2 * p],     ah[mt], bh[0], bh[1]);
                    mma16816(acc[mt][2 * p],     ah[mt], bl[0], bl[1]);
                    mma16816(acc[mt][2 * p],     al[mt], bh[0], bh[1]);
                    mma16816(acc[mt][2 * p + 1], ah[mt], bh[2], bh[3]);
                    mma16816(acc[mt][2 * p + 1], ah[mt], bl[2], bl[3]);
                    mma16816(acc[mt][2 * p + 1], al[mt], bh[2], bh[3]);
                }
            }
        }
    }

    // epilogue
    const int g = lane >> 2, tg = lane & 3;
    #pragma unroll
    for (int mt = 0; mt < 2; mt++) {
        const int rb = m0 + wm + mt * 16 + g;
        #pragma unroll
        for (int nt = 0; nt < 8; nt++) {
            const int col = n0 + wn + nt * 8 + tg * 2;
            const float bv0 = bias[col], bv1 = bias[col + 1];
            #pragma unroll
            for (int hh = 0; hh < 2; hh++) {
                const int row = rb + hh * 8;
                if (row < M) {
                    float v0 = acc[mt][nt][hh * 2]     + bv0;
                    float v1 = acc[mt][nt][hh * 2 + 1] + bv1;
                    if (ACT == 1) { v0 = v0 * normcdff(v0); v1 = v1 * normcdff(v1); }
                    size_t go = (size_t)row * N + col;
                    if (RES) {
                        float2 r2 = *(const float2*)(res + go);
                        v0 += r2.x; v1 += r2.y;
                    }
                    if (OSPLIT) {
                        if (col >= vstart) {
                            __half2 h2, l2;
                            h2.x = __float2half(v0); h2.y = __float2half(v1);
                            l2.x = __float2half(v0 - __half2float(h2.x));
                            l2.y = __float2half(v1 - __half2float(h2.y));
                            *(__half2*)(Chi + go) = h2;
                            *(__half2*)(Clo + go) = l2;
                        } else {
                            __nv_bfloat162 h2, l2;
                            h2.x = __float2bfloat16(v0); h2.y = __float2bfloat16(v1);
                            l2.x = __float2bfloat16(v0 - __bfloat162float(h2.x));
                            l2.y = __float2bfloat16(v1 - __bfloat162float(h2.y));
                            *(__nv_bfloat162*)(Chi + go) = h2;
                            *(__nv_bfloat162*)(Clo + go) = l2;
                        }
                    } else {
                        *(float2*)(C + go) = make_float2(v0, v1);
                    }
                }
            }
        }
    }
}

// ================= scores: 128x128 tile, K=64 in two preloaded chunks, occ=2 =================
#define STG 40960u
__global__ void __launch_bounds__(256, 2) scores_mma(
    const __nv_bfloat16* __restrict__ qkvh, const __nv_bfloat16* __restrict__ qkvl,
    float* __restrict__ dp) {
    extern __shared__ __align__(128) char dsm[];
    const uint32_t sb = smem_u32(dsm);
    const int bh = blockIdx.z;
    const int bb = bh / NH, h = bh % NH;
    const size_t qb = (size_t)bb * T_ * 2304 + h * 64;
    const size_t kb_ = qb + 768;
    float* Cp = dp + (size_t)bh * PTT;
    const int m0 = blockIdx.y * 128, n0 = blockIdx.x * 128;

    const int tid = threadIdx.x;
    const int lane = tid & 31, wid = tid >> 5;
    const int wm = (wid & 3) * 32, wn = (wid >> 2) * 64;
    const int lrow = tid >> 2;
    const int lq   = (tid & 3) * 16;
    const int mi = lane >> 3, r8 = lane & 7;
    const uint32_t aoff = (uint32_t)((wm + (mi & 1) * 8 + r8) * 80 + ((mi >> 1) * 8) * 2);
    const uint32_t boff = (uint32_t)((wn + (mi >> 1) * 8 + r8) * 80 + ((mi & 1) * 8) * 2);

    float acc[2][8][4];
    #pragma unroll
    for (int a = 0; a < 2; a++)
        #pragma unroll
        for (int b = 0; b < 8; b++)
            #pragma unroll
            for (int d = 0; d < 4; d++) acc[a][b][d] = 0.f;

    auto load_chunk = [&](int c) {
        const uint32_t st = sb + (uint32_t)c * STG;
        const int k0 = c << 5;
        #pragma unroll
        for (int i = 0; i < 2; i++) {
            int r = lrow + i * 64;
            int gq = m0 + r; if (gq > T_ - 1) gq = T_ - 1;
            int gk = n0 + r; if (gk > T_ - 1) gk = T_ - 1;
            uint32_t d = st + (uint32_t)(r * 80) + lq;
            cp16(d,          (const char*)(qkvh + qb  + (size_t)gq * 2304 + k0) + lq);
            cp16(d + 10240u, (const char*)(qkvl + qb  + (size_t)gq * 2304 + k0) + lq);
            cp16(d + 20480u, (const char*)(qkvh + kb_ + (size_t)gk * 2304 + k0) + lq);
            cp16(d + 30720u, (const char*)(qkvl + kb_ + (size_t)gk * 2304 + k0) + lq);
        }
    };

    load_chunk(0); CP_COMMIT();
    load_chunk(1); CP_COMMIT();

    #pragma unroll
    for (int c = 0; c < 2; c++) {
        if (c == 0) { CP_WAIT(1); }
        else        { CP_WAIT(0); }
        __syncthreads();
        const uint32_t st = sb + (uint32_t)c * STG;
        #pragma unroll
        for (int kb = 0; kb < 2; kb++) {
            const uint32_t ko = (uint32_t)(kb * 32);
            uint32_t ah[2][4], al[2][4];
            ldsm4(ah[0], st + aoff + ko);
            ldsm4(ah[1], st + aoff + 1280u + ko);
            ldsm4(al[0], st + 10240u + aoff + ko);
            ldsm4(al[1], st + 10240u + aoff + 1280u + ko);
            #pragma unroll
            for (int p = 0; p < 4; p++) {
                uint32_t bh[4], bl[4];
                ldsm4(bh, st + 20480u + boff + (uint32_t)(p * 1280) + ko);
                ldsm4(bl, st + 30720u + boff + (uint32_t)(p * 1280) + ko);
                #pragma unroll
                for (int mt = 0; mt < 2; mt++) {
                    mma16816(acc[mt][2 * p],     ah[mt], bh[0], bh[1]);
                    mma16816(acc[mt][2 * p],     ah[mt], bl[0], bl[1]);
                    mma16816(acc[mt][2 * p],     al[mt], bh[0], bh[1]);
                    mma16816(acc[mt][2 * p + 1], ah[mt], bh[2], bh[3]);
                    mma16816(acc[mt][2 * p + 1], ah[mt], bl[2], bl[3]);
                    mma16816(acc[mt][2 * p + 1], al[mt], bh[2], bh[3]);
                }
            }
        }
    }

    const int g = lane >> 2, tg = lane & 3;
    #pragma unroll
    for (int mt = 0; mt < 2; mt++) {
        const int rb = m0 + wm + mt * 16 + g;
        #pragma unroll
        for (int nt = 0; nt < 8; nt++) {
            const int col = n0 + wn + nt * 8 + tg * 2;
            #pragma unroll
            for (int hh = 0; hh < 2; hh++) {
                const int row = rb + hh * 8;
                if (row < T_ && col < T_) {
                    float v0 = acc[mt][nt][hh * 2]     * 0.125f;
                    float v1 = acc[mt][nt][hh * 2 + 1] * 0.125f;
                    size_t go = (size_t)row * KPAD + col;
                    if (col + 1 < T_) *(float2*)(Cp + go) = make_float2(v0, v1);
                    else Cp[go] = v0;
                }
            }
        }
    }
}

// ---------------- softmax over HEADS -> fp16 probs (x4 vectorized) ----------------
__global__ void softmax_fp16(const float* __restrict__ dp,
                             __half* __restrict__ phi) {
    long long idx = (long long)blockIdx.x * blockDim.x + threadIdx.x;
    const long long tot = (long long)B_ * (PTT / 4);
    if (idx >= tot) return;
    const int b  = (int)(idx / (PTT / 4));
    const int r4 = (int)(idx % (PTT / 4));
    size_t base = (size_t)b * NH * PTT + (size_t)r4 * 4;
    float4 v[NH];
    float4 mx = make_float4(-1e30f, -1e30f, -1e30f, -1e30f);
    #pragma unroll
    for (int h = 0; h < NH; h++) {
        v[h] = *(const float4*)(dp + base + (size_t)h * PTT);
        mx.x = fmaxf(mx.x, v[h].x); mx.y = fmaxf(mx.y, v[h].y);
        mx.z = fmaxf(mx.z, v[h].z); mx.w = fmaxf(mx.w, v[h].w);
    }
    float4 s = make_float4(0.f, 0.f, 0.f, 0.f);
    #pragma unroll
    for (int h = 0; h < NH; h++) {
        v[h].x = expf(v[h].x - mx.x); s.x += v[h].x;
        v[h].y = expf(v[h].y - mx.y); s.y += v[h].y;
        v[h].z = expf(v[h].z - mx.z); s.z += v[h].z;
        v[h].w = expf(v[h].w - mx.w); s.w += v[h].w;
    }
    s.x = 1.f / s.x; s.y = 1.f / s.y; s.z = 1.f / s.z; s.w = 1.f / s.w;
    #pragma unroll
    for (int h = 0; h < NH; h++) {
        __half2 h0, h1;
        h0.x = __float2half(v[h].x * s.x); h0.y = __float2half(v[h].y * s.y);
        h1.x = __float2half(v[h].z * s.z); h1.y = __float2half(v[h].w * s.w);
        size_t o = base + (size_t)h * PTT;
        *(__half2*)(phi + o)     = h0;
        *(__half2*)(phi + o + 2) = h1;
    }
}

// ---------------- wa = P(fp16) @ V(fp16 split), 2 MMA passes, occ=2, prefetch-first ----------------
#define STGW 19456u
__global__ void __launch_bounds__(256, 2) wa_mma(
    const __half* __restrict__ phi,
    const __nv_bfloat16* __restrict__ qkvh, const __nv_bfloat16* __restrict__ qkvl,
    __nv_bfloat16* __restrict__ whi, __nv_bfloat16* __restrict__ wlo) {
    extern __shared__ __align__(128) char dsm[];
    const uint32_t sb = smem_u32(dsm);
    const int tid = threadIdx.x;
    const int lane = tid & 31, wid = tid >> 5;
    const int bh = blockIdx.y;
    const int b = bh / NH, h = bh % NH;
    const int q0 = blockIdx.x * 128;
    const int wm = (wid & 3) * 32, wn = (wid >> 2) * 32;
    const int lrow = tid >> 2;
    const int lq   = (tid & 3) * 16;
    const int mi = lane >> 3, r8 = lane & 7;
    const uint32_t aoff = (uint32_t)((wm + (mi & 1) * 8 + r8) * 80 + ((mi >> 1) * 8) * 2);
    const uint32_t voff = (uint32_t)(((mi & 1) * 8 + r8) * 144 + (wn + (mi >> 1) * 8) * 2);

    const size_t pbase = (size_t)bh * PTT;
    const __half* Vh = (const __half*)(qkvh + (size_t)b * T_ * 2304 + 1536 + h * 64);
    const __half* Vl = (const __half*)(qkvl + (size_t)b * T_ * 2304 + 1536 + h * 64);

    float acc[2][4][4];
    #pragma unroll
    for (int a = 0; a < 2; a++)
        #pragma unroll
        for (int n = 0; n < 4; n++)
            #pragma unroll
            for (int d = 0; d < 4; d++) acc[a][n][d] = 0.f;

    const int nc = (T_ + 31) / 32;  // 19

    auto load_chunk = [&](int c) {
        const uint32_t st = sb + (uint32_t)(c % 3) * STGW;
        const int k0 = c * 32;
        #pragma unroll
        for (int i = 0; i < 2; i++) {
            int r = lrow + i * 64;
            int q = q0 + r; if (q > T_ - 1) q = T_ - 1;
            int kstart = k0 + (lq >> 1);
            int nb = (T_ - kstart) * 2;
            nb = nb < 0 ? 0 : (nb > 16 ? 16 : nb);
            size_t off = pbase + (size_t)q * KPAD + k0;
            cp16z(st + (uint32_t)(r * 80) + lq, (const char*)(phi + off) + lq, nb);
        }
        {
            int vr = tid >> 3, vq = (tid & 7) * 16;
            int k = k0 + vr;
            int nb = (k < T_) ? 16 : 0;
            if (k > T_ - 1) k = T_ - 1;
            size_t off = (size_t)k * 2304;
            uint32_t d = st + 10240u + (uint32_t)(vr * 144) + vq;
            cp16z(d,         (const char*)(Vh + off) + vq, nb);
            cp16z(d + 4608u, (const char*)(Vl + off) + vq, nb);
        }
    };

    load_chunk(0); CP_COMMIT();
    load_chunk(1); CP_COMMIT();

    for (int c = 0; c < nc; c++) {
        CP_WAIT(1);
        __syncthreads();
        if (c + 2 < nc) load_chunk(c + 2);   // prefetch BEFORE compute (3 buffers make this safe)
        CP_COMMIT();
        const uint32_t st = sb + (uint32_t)(c % 3) * STGW;
        #pragma unroll
        for (int ks = 0; ks < 2; ks++) {
            const uint32_t ko = (uint32_t)(ks * 32);
            uint32_t a[2][4];
            ldsm4(a[0], st + aoff + ko);
            ldsm4(a[1], st + aoff + 1280u + ko);
            uint32_t vh0[4], vh1[4], vl0[4], vl1[4];
            const uint32_t vb = st + 10240u + voff + (uint32_t)(ks * 2304);
            ldsm4t(vh0, vb);
            ldsm4t(vh1, vb + 32u);
            ldsm4t(vl0, vb + 4608u);
            ldsm4t(vl1, vb + 4608u + 32u);
            #pragma unroll
            for (int mt = 0; mt < 2; mt++) {
                mma16816h(acc[mt][0], a[mt], vh0[0], vh0[1]);
                mma16816h(acc[mt][0], a[mt], vl0[0], vl0[1]);
                mma16816h(acc[mt][1], a[mt], vh0[2], vh0[3]);
                mma16816h(acc[mt][1], a[mt], vl0[2], vl0[3]);
                mma16816h(acc[mt][2], a[mt], vh1[0], vh1[1]);
                mma16816h(acc[mt][2], a[mt], vl1[0], vl1[1]);
                mma16816h(acc[mt][3], a[mt], vh1[2], vh1[3]);
                mma16816h(acc[mt][3], a[mt], vl1[2], vl1[3]);
            }
        }
    }

    const int g = lane >> 2, tg = lane & 3;
    #pragma unroll
    for (int mt = 0; mt < 2; mt++) {
        #pragma unroll
        for (int nt = 0; nt < 4; nt++) {
            const int col = wn + nt * 8 + tg * 2;
            #pragma unroll
            for (int hh = 0; hh < 2; hh++) {
                const int row = q0 + wm + mt * 16 + g + hh * 8;
                if (row < T_) {
                    float v0 = acc[mt][nt][hh * 2];
                    float v1 = acc[mt][nt][hh * 2 + 1];
                    size_t go = ((size_t)(b * T_ + row)) * D_ + h * 64 + col;
                    __nv_bfloat162 h2, l2;
                    h2.x = __float2bfloat16(v0); h2.y = __float2bfloat16(v1);
                    l2.x = __float2bfloat16(v0 - __bfloat162float(h2.x));
                    l2.y = __float2bfloat16(v1 - __bfloat162float(h2.y));
                    *(__nv_bfloat162*)(whi + go) = h2;
                    *(__nv_bfloat162*)(wlo + go) = l2;
                }
            }
        }
    }
}

// ---------------- host launch ----------------
extern "C" void kernel_launch(void* const* d_in, const int* in_sizes, int n_in,
                              void* d_out, int out_size) {
    const float* x      = (const float*)d_in[0];
    const float* ln1_w  = (const float*)d_in[1];
    const float* ln1_b  = (const float*)d_in[2];
    const float* qkv_w  = (const float*)d_in[3];
    const float* qkv_b  = (const float*)d_in[4];
    const float* proj_w = (const float*)d_in[5];
    const float* proj_b = (const float*)d_in[6];
    const float* ln2_w  = (const float*)d_in[7];
    const float* ln2_b  = (const float*)d_in[8];
    const float* fc1_w  = (const float*)d_in[9];
    const float* fc1_b  = (const float*)d_in[10];
    const float* fc2_w  = (const float*)d_in[11];
    const float* fc2_b  = (const float*)d_in[12];
    float* out = (float*)d_out;

    __nv_bfloat16 *yhi, *ylo, *qkh, *qkl, *wahi, *walo, *hhi, *hlo;
    __nv_bfloat16 *wqh, *wql, *wph, *wpl, *w1h, *w1l, *w2h, *w2l;
    __half *ph;
    float *dpb, *x1b;
    cudaGetSymbolAddress((void**)&yhi,  g_y_hi);
    cudaGetSymbolAddress((void**)&ylo,  g_y_lo);
    cudaGetSymbolAddress((void**)&qkh,  g_qkv_hi);
    cudaGetSymbolAddress((void**)&qkl,  g_qkv_lo);
    cudaGetSymbolAddress((void**)&dpb,  g_dp);
    cudaGetSymbolAddress((void**)&ph,   g_p);
    cudaGetSymbolAddress((void**)&wahi, g_wa_hi);
    cudaGetSymbolAddress((void**)&walo, g_wa_lo);
    cudaGetSymbolAddress((void**)&x1b,  g_x1);
    cudaGetSymbolAddress((void**)&hhi,  g_h_hi);
    cudaGetSymbolAddress((void**)&hlo,  g_h_lo);
    cudaGetSymbolAddress((void**)&wqh,  g_wq_hi);
    cudaGetSymbolAddress((void**)&wql,  g_wq_lo);
    cudaGetSymbolAddress((void**)&wph,  g_wp_hi);
    cudaGetSymbolAddress((void**)&wpl,  g_wp_lo);
    cudaGetSymbolAddress((void**)&w1h,  g_w1_hi);
    cudaGetSymbolAddress((void**)&w1l,  g_w1_lo);
    cudaGetSymbolAddress((void**)&w2h,  g_w2_hi);
    cudaGetSymbolAddress((void**)&w2l,  g_w2_lo);

    const int SMEM_L = 3 * (int)STG3;      // 98304
    const int SMEM_S = 2 * (int)STG;       // 81920
    const int SMEM_W = 3 * (int)STGW;      // 58368
    cudaFuncSetAttribute(gemm_lin<0, false, true >, cudaFuncAttributeMaxDynamicSharedMemorySize, SMEM_L);
    cudaFuncSetAttribute(gemm_lin<0, true,  false>, cudaFuncAttributeMaxDynamicSharedMemorySize, SMEM_L);
    cudaFuncSetAttribute(gemm_lin<1, false, true >, cudaFuncAttributeMaxDynamicSharedMemorySize, SMEM_L);
    cudaFuncSetAttribute(scores_mma,  cudaFuncAttributeMaxDynamicSharedMemorySize, SMEM_S);
    cudaFuncSetAttribute(wa_mma,      cudaFuncAttributeMaxDynamicSharedMemorySize, SMEM_W);

    const int MT = (BT + 127) / 128;  // 145

    wconv_kernel<<<dim3(2304 / 32, 768 / 32),  dim3(32, 8)>>>(qkv_w,  wqh, wql, 768,  2304);
    wconv_kernel<<<dim3(768 / 32,  768 / 32),  dim3(32, 8)>>>(proj_w, wph, wpl, 768,  768);
    wconv_kernel<<<dim3(3072 / 32, 768 / 32),  dim3(32, 8)>>>(fc1_w,  w1h, w1l, 768,  3072);
    wconv_kernel<<<dim3(768 / 32,  3072 / 32), dim3(32, 8)>>>(fc2_w,  w2h, w2l, 3072, 768);

    // 1) LN1 -> split
    ln_kernel<<<BT, 256>>>(x, ln1_w, ln1_b, yhi, ylo);
    // 2) QKV projection -> split qkv (Q,K bf16 split; V fp16 split)
    gemm_lin<0, false, true><<<dim3(2304 / 128, MT), 256, SMEM_L>>>(
        yhi, ylo, wqh, wql, qkv_b, nullptr, nullptr, qkh, qkl, BT, 2304, D_, 1536);
    // 3) scores -> fp32 dp (padded rows)
    scores_mma<<<dim3(5, 5, B_ * NH), 256, SMEM_S>>>(qkh, qkl, dpb);
    // 4) softmax over heads -> fp16 probs
    {
        long long total = (long long)B_ * (PTT / 4);
        int grid = (int)((total + 255) / 256);
        softmax_fp16<<<grid, 256>>>(dpb, ph);
    }
    // 5) wa = P(fp16) @ V(fp16 split) -> bf16 split
    wa_mma<<<dim3(5, B_ * NH), 256, SMEM_W>>>(ph, qkh, qkl, wahi, walo);
    // 6) output projection + residual
    gemm_lin<0, true, false><<<dim3(D_ / 128, MT), 256, SMEM_L>>>(
        wahi, walo, wph, wpl, proj_b, x, x1b, nullptr, nullptr, BT, D_, D_, 1 << 30);
    // 7) LN2 -> split
    ln_kernel<<<BT, 256>>>(x1b, ln2_w, ln2_b, yhi, ylo);
    // 8) fc1 + exact GELU -> split
    gemm_lin<1, false, true><<<dim3(H_ / 128, MT), 256, SMEM_L>>>(
        yhi, ylo, w1h, w1l, fc1_b, nullptr, nullptr, hhi, hlo, BT, H_, D_, 1 << 30);
    // 9) fc2 + residual -> output
    gemm_lin<0, true, false><<<dim3(D_ / 128, MT), 256, SMEM_L>>>(
        hhi, hlo, w2h, w2l, fc2_b, x1b, out, nullptr, nullptr, BT, D_, H_, 1 << 30);
}

// round 15
// speedup vs baseline: 1.1971x; 1.1971x over previous
#include <cuda_runtime.h>
#include <cuda_bf16.h>
#include <cuda_fp16.h>
#include <math.h>
#include <stdint.h>

#define BT   18464          // B*T
#define B_   32
#define T_   577
#define D_   768
#define H_   3072
#define NH   12
#define KPAD 584            // padded key dim for dp/probs rows (16B-aligned)
#define PTT  (T_ * KPAD)    // per-(b,h) plane size (divisible by 4)

// ---------------- static scratch ----------------
__device__ __nv_bfloat16 g_y_hi [(size_t)BT * D_];   // LN1: bf16 hi; LN2: fp16 single (bits)
__device__ __nv_bfloat16 g_y_lo [(size_t)BT * D_];
__device__ __nv_bfloat16 g_qkv_hi[(size_t)BT * 2304];  // V cols [1536,2304) hold fp16 bits
__device__ __nv_bfloat16 g_qkv_lo[(size_t)BT * 2304];
__device__ float         g_dp   [(size_t)B_ * NH * PTT];
__device__ __half        g_p    [(size_t)B_ * NH * PTT];
__device__ __nv_bfloat16 g_wa_hi[(size_t)BT * D_];
__device__ __nv_bfloat16 g_wa_lo[(size_t)BT * D_];
__device__ float         g_x1   [(size_t)BT * D_];
__device__ __half        g_h16  [(size_t)BT * H_];   // MLP hidden, fp16 single
__device__ __nv_bfloat16 g_wq_hi[2304 * 768], g_wq_lo[2304 * 768];
__device__ __nv_bfloat16 g_wp_hi[ 768 * 768], g_wp_lo[ 768 * 768];
__device__ __half        g_w1_hi[3072 * 768], g_w1_lo[3072 * 768];   // fp16 split
__device__ __half        g_w2_hi[ 768 * 3072], g_w2_lo[ 768 * 3072]; // fp16 split

// ---------------- helpers ----------------
__device__ __forceinline__ uint32_t smem_u32(const void* p) {
    uint32_t a;
    asm("{ .reg .u64 t; cvta.to.shared.u64 t, %1; cvt.u32.u64 %0, t; }" : "=r"(a) : "l"(p));
    return a;
}
__device__ __forceinline__ void cp16(uint32_t dst, const void* src) {
    asm volatile("cp.async.cg.shared.global [%0], [%1], 16;" :: "r"(dst), "l"(src));
}
__device__ __forceinline__ void cp16z(uint32_t dst, const void* src, int nb) {
    asm volatile("cp.async.cg.shared.global [%0], [%1], 16, %2;" :: "r"(dst), "l"(src), "r"(nb));
}
#define CP_COMMIT() asm volatile("cp.async.commit_group;" ::: "memory")
#define CP_WAIT(n)  asm volatile("cp.async.wait_group %0;" :: "n"(n) : "memory")

__device__ __forceinline__ void ldsm4(uint32_t* r, uint32_t a) {
    asm volatile("ldmatrix.sync.aligned.m8n8.x4.shared.b16 {%0,%1,%2,%3}, [%4];"
                 : "=r"(r[0]), "=r"(r[1]), "=r"(r[2]), "=r"(r[3]) : "r"(a));
}
__device__ __forceinline__ void ldsm4t(uint32_t* r, uint32_t a) {
    asm volatile("ldmatrix.sync.aligned.m8n8.x4.trans.shared.b16 {%0,%1,%2,%3}, [%4];"
                 : "=r"(r[0]), "=r"(r[1]), "=r"(r[2]), "=r"(r[3]) : "r"(a));
}
__device__ __forceinline__ void mma16816(float* c, const uint32_t* a, uint32_t b0, uint32_t b1) {
    asm volatile("mma.sync.aligned.m16n8k16.row.col.f32.bf16.bf16.f32 "
                 "{%0,%1,%2,%3}, {%4,%5,%6,%7}, {%8,%9}, {%0,%1,%2,%3};"
                 : "+f"(c[0]), "+f"(c[1]), "+f"(c[2]), "+f"(c[3])
                 : "r"(a[0]), "r"(a[1]), "r"(a[2]), "r"(a[3]), "r"(b0), "r"(b1));
}
__device__ __forceinline__ void mma16816h(float* c, const uint32_t* a, uint32_t b0, uint32_t b1) {
    asm volatile("mma.sync.aligned.m16n8k16.row.col.f32.f16.f16.f32 "
                 "{%0,%1,%2,%3}, {%4,%5,%6,%7}, {%8,%9}, {%0,%1,%2,%3};"
                 : "+f"(c[0]), "+f"(c[1]), "+f"(c[2]), "+f"(c[3])
                 : "r"(a[0]), "r"(a[1]), "r"(a[2]), "r"(a[3]), "r"(b0), "r"(b1));
}

// ---------------- weight transpose+split (bf16) ----------------
__global__ void wconv_kernel(const float* __restrict__ W,
                             __nv_bfloat16* __restrict__ hi,
                             __nv_bfloat16* __restrict__ lo, int K, int N) {
    __shared__ float t[32][33];
    const int k0 = blockIdx.y * 32, n0 = blockIdx.x * 32;
    #pragma unroll
    for (int i = 0; i < 4; i++)
        t[threadIdx.y + i * 8][threadIdx.x] =
            W[(size_t)(k0 + threadIdx.y + i * 8) * N + n0 + threadIdx.x];
    __syncthreads();
    #pragma unroll
    for (int i = 0; i < 4; i++) {
        int n = n0 + threadIdx.y + i * 8;
        int k = k0 + threadIdx.x;
        float x = t[threadIdx.x][threadIdx.y + i * 8];
        __nv_bfloat16 h = __float2bfloat16(x);
        hi[(size_t)n * K + k] = h;
        lo[(size_t)n * K + k] = __float2bfloat16(x - __bfloat162float(h));
    }
}

// ---------------- weight transpose+split (fp16) ----------------
__global__ void wconv_h_kernel(const float* __restrict__ W,
                               __half* __restrict__ hi,
                               __half* __restrict__ lo, int K, int N) {
    __shared__ float t[32][33];
    const int k0 = blockIdx.y * 32, n0 = blockIdx.x * 32;
    #pragma unroll
    for (int i = 0; i < 4; i++)
        t[threadIdx.y + i * 8][threadIdx.x] =
            W[(size_t)(k0 + threadIdx.y + i * 8) * N + n0 + threadIdx.x];
    __syncthreads();
    #pragma unroll
    for (int i = 0; i < 4; i++) {
        int n = n0 + threadIdx.y + i * 8;
        int k = k0 + threadIdx.x;
        float x = t[threadIdx.x][threadIdx.y + i * 8];
        __half h = __float2half(x);
        hi[(size_t)n * K + k] = h;
        lo[(size_t)n * K + k] = __float2half(x - __half2float(h));
    }
}

// ---------------- LayerNorm -> split bf16 (LN1) ----------------
__global__ void __launch_bounds__(256) ln_kernel(const float* __restrict__ x,
                                                 const float* __restrict__ w,
                                                 const float* __restrict__ b,
                                                 __nv_bfloat16* __restrict__ yhi,
                                                 __nv_bfloat16* __restrict__ ylo) {
    const int row = blockIdx.x;
    const float* xr = x + (size_t)row * D_;
    const int tid = threadIdx.x;

    float v0 = xr[tid], v1 = xr[tid + 256], v2 = xr[tid + 512];
    float s  = v0 + v1 + v2;
    float s2 = v0 * v0 + v1 * v1 + v2 * v2;
    #pragma unroll
    for (int o = 16; o > 0; o >>= 1) {
        s  += __shfl_xor_sync(0xffffffffu, s,  o);
        s2 += __shfl_xor_sync(0xffffffffu, s2, o);
    }
    __shared__ float sh[8], sh2[8];
    const int wi = tid >> 5, ln = tid & 31;
    if (ln == 0) { sh[wi] = s; sh2[wi] = s2; }
    __syncthreads();
    if (wi == 0) {
        s  = (ln < 8) ? sh[ln]  : 0.f;
        s2 = (ln < 8) ? sh2[ln] : 0.f;
        #pragma unroll
        for (int o = 4; o > 0; o >>= 1) {
            s  += __shfl_xor_sync(0xffffffffu, s,  o);
            s2 += __shfl_xor_sync(0xffffffffu, s2, o);
        }
        if (ln == 0) { sh[0] = s; sh2[0] = s2; }
    }
    __syncthreads();
    const float mu  = sh[0] * (1.0f / D_);
    const float var = sh2[0] * (1.0f / D_) - mu * mu;
    const float rs  = rsqrtf(var + 1e-6f);
    size_t base = (size_t)row * D_;
    #pragma unroll
    for (int j = 0; j < 3; j++) {
        int c = tid + j * 256;
        float v = (j == 0 ? v0 : (j == 1 ? v1 : v2));
        float y = (v - mu) * rs * w[c] + b[c];
        __nv_bfloat16 h = __float2bfloat16(y);
        yhi[base + c] = h;
        ylo[base + c] = __float2bfloat16(y - __bfloat162float(h));
    }
}

// ---------------- LayerNorm -> fp16 single (LN2) ----------------
__global__ void __launch_bounds__(256) ln_fp16_kernel(const float* __restrict__ x,
                                                      const float* __restrict__ w,
                                                      const float* __restrict__ b,
                                                      __half* __restrict__ y16) {
    const int row = blockIdx.x;
    const float* xr = x + (size_t)row * D_;
    const int tid = threadIdx.x;

    float v0 = xr[tid], v1 = xr[tid + 256], v2 = xr[tid + 512];
    float s  = v0 + v1 + v2;
    float s2 = v0 * v0 + v1 * v1 + v2 * v2;
    #pragma unroll
    for (int o = 16; o > 0; o >>= 1) {
        s  += __shfl_xor_sync(0xffffffffu, s,  o);
        s2 += __shfl_xor_sync(0xffffffffu, s2, o);
    }
    __shared__ float sh[8], sh2[8];
    const int wi = tid >> 5, ln = tid & 31;
    if (ln == 0) { sh[wi] = s; sh2[wi] = s2; }
    __syncthreads();
    if (wi == 0) {
        s  = (ln < 8) ? sh[ln]  : 0.f;
        s2 = (ln < 8) ? sh2[ln] : 0.f;
        #pragma unroll
        for (int o = 4; o > 0; o >>= 1) {
            s  += __shfl_xor_sync(0xffffffffu, s,  o);
            s2 += __shfl_xor_sync(0xffffffffu, s2, o);
        }
        if (ln == 0) { sh[0] = s; sh2[0] = s2; }
    }
    __syncthreads();
    const float mu  = sh[0] * (1.0f / D_);
    const float var = sh2[0] * (1.0f / D_) - mu * mu;
    const float rs  = rsqrtf(var + 1e-6f);
    size_t base = (size_t)row * D_;
    #pragma unroll
    for (int j = 0; j < 3; j++) {
        int c = tid + j * 256;
        float v = (j == 0 ? v0 : (j == 1 ? v1 : v2));
        y16[base + c] = __float2half((v - mu) * rs * w[c] + b[c]);
    }
}

// ================= 3-pass bf16 linear GEMM (qkv, proj): round-13 proven =================
#define STG3 32768u
template <int ACT, bool RES, bool OSPLIT>
__global__ void __launch_bounds__(256, 2) gemm_lin(
    const __nv_bfloat16* __restrict__ Ahi, const __nv_bfloat16* __restrict__ Alo,
    const __nv_bfloat16* __restrict__ Whi, const __nv_bfloat16* __restrict__ Wlo,
    const float* __restrict__ bias, const float* __restrict__ res,
    float* __restrict__ C, __nv_bfloat16* __restrict__ Chi, __nv_bfloat16* __restrict__ Clo,
    int M, int N, int K, int vstart) {
    extern __shared__ __align__(128) char dsm[];
    const uint32_t sb = smem_u32(dsm);
    const int tid = threadIdx.x;
    const int lane = tid & 31, wid = tid >> 5;
    const int m0 = blockIdx.y * 128, n0 = blockIdx.x * 128;
    const int wm = (wid & 3) * 32, wn = (wid >> 2) * 64;
    const int lrow = tid >> 2;
    const int lseg = tid & 3;
    const int mi = lane >> 3, r8 = lane & 7;
    const uint32_t xr_ = (uint32_t)((r8 >> 1) & 3);
    const int a_row = wm + (mi & 1) * 8 + r8;
    const int b_row = wn + (mi >> 1) * 8 + r8;
    const uint32_t aoff = (uint32_t)(a_row * 64) + ((((uint32_t)(mi >> 1)) ^ xr_) << 4);
    const uint32_t boff = (uint32_t)(b_row * 64) + ((((uint32_t)(mi & 1)) ^ xr_) << 4);

    float acc[2][8][4];
    #pragma unroll
    for (int a = 0; a < 2; a++)
        #pragma unroll
        for (int b = 0; b < 8; b++)
            #pragma unroll
            for (int d = 0; d < 4; d++) acc[a][b][d] = 0.f;

    const int nc = K >> 5;

    auto load_chunk = [&](int c) {
        const uint32_t st = sb + (uint32_t)(c % 3) * STG3;
        const int k0 = c << 5;
        #pragma unroll
        for (int i = 0; i < 2; i++) {
            int r = lrow + i * 64;
            uint32_t dseg = (uint32_t)lseg ^ (uint32_t)((r >> 1) & 3);
            uint32_t d = st + (uint32_t)(r * 64) + (dseg << 4);
            int gr = m0 + r; if (gr > M - 1) gr = M - 1;
            size_t gb = (size_t)(n0 + r) * K + k0;
            cp16(d,          (const char*)(Ahi + (size_t)gr * K + k0) + lseg * 16);
            cp16(d + 8192u,  (const char*)(Alo + (size_t)gr * K + k0) + lseg * 16);
            cp16(d + 16384u, (const char*)(Whi + gb) + lseg * 16);
            cp16(d + 24576u, (const char*)(Wlo + gb) + lseg * 16);
        }
    };

    load_chunk(0); CP_COMMIT();
    if (nc > 1) load_chunk(1);
    CP_COMMIT();

    for (int c = 0; c < nc; c++) {
        CP_WAIT(1);
        __syncthreads();
        if (c + 2 < nc) load_chunk(c + 2);
        CP_COMMIT();
        const uint32_t st = sb + (uint32_t)(c % 3) * STG3;
        #pragma unroll
        for (int kb = 0; kb < 2; kb++) {
            const uint32_t kx = (uint32_t)(kb * 32);
            uint32_t ah[2][4], al[2][4];
            ldsm4(ah[0], (st + aoff) ^ kx);
            ldsm4(ah[1], (st + aoff + 1024u) ^ kx);
            ldsm4(al[0], (st + 8192u + aoff) ^ kx);
            ldsm4(al[1], (st + 8192u + aoff + 1024u) ^ kx);
            #pragma unroll
            for (int p = 0; p < 4; p++) {
                uint32_t bh[4], bl[4];
                ldsm4(bh, (st + 16384u + boff + (uint32_t)(p * 1024)) ^ kx);
                ldsm4(bl, (st + 24576u + boff + (uint32_t)(p * 1024)) ^ kx);
                #pragma unroll
                for (int mt = 0; mt < 2; mt++) {
                    mma16816(acc[mt][2 * p],     ah[mt], bh[0], bh[1]);
                    mma16816(acc[mt][2 * p],     ah[mt], bl[0], bl[1]);
                    mma16816(acc[mt][2 * p],     al[mt], bh[0], bh[1]);
                    mma16816(acc[mt][2 * p + 1], ah[mt], bh[2], bh[3]);
                    mma16816(acc[mt][2 * p + 1], ah[mt], bl[2], bl[3]);
                    mma16816(acc[mt][2 * p + 1], al[mt], bh[2], bh[3]);
                }
            }
        }
    }

    const int g = lane >> 2, tg = lane & 3;
    #pragma unroll
    for (int mt = 0; mt < 2; mt++) {
        const int rb = m0 + wm + mt * 16 + g;
        #pragma unroll
        for (int nt = 0; nt < 8; nt++) {
            const int col = n0 + wn + nt * 8 + tg * 2;
            const float bv0 = bias[col], bv1 = bias[col + 1];
            #pragma unroll
            for (int hh = 0; hh < 2; hh++) {
                const int row = rb + hh * 8;
                if (row < M) {
                    float v0 = acc[mt][nt][hh * 2]     + bv0;
                    float v1 = acc[mt][nt][hh * 2 + 1] + bv1;
                    if (ACT == 1) { v0 = v0 * normcdff(v0); v1 = v1 * normcdff(v1); }
                    size_t go = (size_t)row * N + col;
                    if (RES) {
                        float2 r2 = *(const float2*)(res + go);
                        v0 += r2.x; v1 += r2.y;
                    }
                    if (OSPLIT) {
                        if (col >= vstart) {
                            __half2 h2, l2;
                            h2.x = __float2half(v0); h2.y = __float2half(v1);
                            l2.x = __float2half(v0 - __half2float(h2.x));
                            l2.y = __float2half(v1 - __half2float(h2.y));
                            *(__half2*)(Chi + go) = h2;
                            *(__half2*)(Clo + go) = l2;
                        } else {
                            __nv_bfloat162 h2, l2;
                            h2.x = __float2bfloat16(v0); h2.y = __float2bfloat16(v1);
                            l2.x = __float2bfloat16(v0 - __bfloat162float(h2.x));
                            l2.y = __float2bfloat16(v1 - __bfloat162float(h2.y));
                            *(__nv_bfloat162*)(Chi + go) = h2;
                            *(__nv_bfloat162*)(Clo + go) = l2;
                        }
                    } else {
                        *(float2*)(C + go) = make_float2(v0, v1);
                    }
                }
            }
        }
    }
}

// ================= 2-pass fp16 GEMM (fc1/fc2): A single fp16, W fp16 hi/lo =================
// stage: A@0 (8KB), Wh@8192, Wl@16384; stage=24576. Same swizzle & 3-stage single-sync loop.
#define STGH 24576u
template <int ACT, bool RES, bool OUTH>
__global__ void __launch_bounds__(256, 2) gemm_hs(
    const __half* __restrict__ A,
    const __half* __restrict__ Whh, const __half* __restrict__ Wll,
    const float* __restrict__ bias, const float* __restrict__ res,
    float* __restrict__ C, __half* __restrict__ Ch,
    int M, int N, int K) {
    extern __shared__ __align__(128) char dsm[];
    const uint32_t sb = smem_u32(dsm);
    const int tid = threadIdx.x;
    const int lane = tid & 31, wid = tid >> 5;
    const int m0 = blockIdx.y * 128, n0 = blockIdx.x * 128;
    const int wm = (wid & 3) * 32, wn = (wid >> 2) * 64;
    const int lrow = tid >> 2;
    const int lseg = tid & 3;
    const int mi = lane >> 3, r8 = lane & 7;
    const uint32_t xr_ = (uint32_t)((r8 >> 1) & 3);
    const int a_row = wm + (mi & 1) * 8 + r8;
    const int b_row = wn + (mi >> 1) * 8 + r8;
    const uint32_t aoff = (uint32_t)(a_row * 64) + ((((uint32_t)(mi >> 1)) ^ xr_) << 4);
    const uint32_t boff = (uint32_t)(b_row * 64) + ((((uint32_t)(mi & 1)) ^ xr_) << 4);

    float acc[2][8][4];
    #pragma unroll
    for (int a = 0; a < 2; a++)
        #pragma unroll
        for (int b = 0; b < 8; b++)
            #pragma unroll
            for (int d = 0; d < 4; d++) acc[a][b][d] = 0.f;

    const int nc = K >> 5;

    auto load_chunk = [&](int c) {
        const uint32_t st = sb + (uint32_t)(c % 3) * STGH;
        const int k0 = c << 5;
        #pragma unroll
        for (int i = 0; i < 2; i++) {
            int r = lrow + i * 64;
            uint32_t dseg = (uint32_t)lseg ^ (uint32_t)((r >> 1) & 3);
            uint32_t d = st + (uint32_t)(r * 64) + (dseg << 4);
            int gr = m0 + r; if (gr > M - 1) gr = M - 1;
            size_t gb = (size_t)(n0 + r) * K + k0;
            cp16(d,          (const char*)(A   + (size_t)gr * K + k0) + lseg * 16);
            cp16(d + 8192u,  (const char*)(Whh + gb) + lseg * 16);
            cp16(d + 16384u, (const char*)(Wll + gb) + lseg * 16);
        }
    };

    load_chunk(0); CP_COMMIT();
    if (nc > 1) load_chunk(1);
    CP_COMMIT();

    for (int c = 0; c < nc; c++) {
        CP_WAIT(1);
        __syncthreads();
        if (c + 2 < nc) load_chunk(c + 2);
        CP_COMMIT();
        const uint32_t st = sb + (uint32_t)(c % 3) * STGH;
        #pragma unroll
        for (int kb = 0; kb < 2; kb++) {
            const uint32_t kx = (uint32_t)(kb * 32);
            uint32_t a_[2][4];
            ldsm4(a_[0], (st + aoff) ^ kx);
            ldsm4(a_[1], (st + aoff + 1024u) ^ kx);
            #pragma unroll
            for (int p = 0; p < 4; p++) {
                uint32_t bh[4], bl[4];
                ldsm4(bh, (st + 8192u  + boff + (uint32_t)(p * 1024)) ^ kx);
                ldsm4(bl, (st + 16384u + boff + (uint32_t)(p * 1024)) ^ kx);
                #pragma unroll
                for (int mt = 0; mt < 2; mt++) {
                    mma16816h(acc[mt][2 * p],     a_[mt], bh[0], bh[1]);
                    mma16816h(acc[mt][2 * p],     a_[mt], bl[0], bl[1]);
                    mma16816h(acc[mt][2 * p + 1], a_[mt], bh[2], bh[3]);
                    mma16816h(acc[mt][2 * p + 1], a_[mt], bl[2], bl[3]);
                }
            }
        }
    }

    const int g = lane >> 2, tg = lane & 3;
    #pragma unroll
    for (int mt = 0; mt < 2; mt++) {
        const int rb = m0 + wm + mt * 16 + g;
        #pragma unroll
        for (int nt = 0; nt < 8; nt++) {
            const int col = n0 + wn + nt * 8 + tg * 2;
            const float bv0 = bias[col], bv1 = bias[col + 1];
            #pragma unroll
            for (int hh = 0; hh < 2; hh++) {
                const int row = rb + hh * 8;
                if (row < M) {
                    float v0 = acc[mt][nt][hh * 2]     + bv0;
                    float v1 = acc[mt][nt][hh * 2 + 1] + bv1;
                    if (ACT == 1) { v0 = v0 * normcdff(v0); v1 = v1 * normcdff(v1); }
                    size_t go = (size_t)row * N + col;
                    if (RES) {
                        float2 r2 = *(const float2*)(res + go);
                        v0 += r2.x; v1 += r2.y;
                    }
                    if (OUTH) {
                        __half2 h2;
                        h2.x = __float2half(v0); h2.y = __float2half(v1);
                        *(__half2*)(Ch + go) = h2;
                    } else {
                        *(float2*)(C + go) = make_float2(v0, v1);
                    }
                }
            }
        }
    }
}

// ================= scores: 128x128 tile, K=64 in two preloaded chunks, occ=2 =================
#define STG 40960u
__global__ void __launch_bounds__(256, 2) scores_mma(
    const __nv_bfloat16* __restrict__ qkvh, const __nv_bfloat16* __restrict__ qkvl,
    float* __restrict__ dp) {
    extern __shared__ __align__(128) char dsm[];
    const uint32_t sb = smem_u32(dsm);
    const int bh = blockIdx.z;
    const int bb = bh / NH, h = bh % NH;
    const size_t qb = (size_t)bb * T_ * 2304 + h * 64;
    const size_t kb_ = qb + 768;
    float* Cp = dp + (size_t)bh * PTT;
    const int m0 = blockIdx.y * 128, n0 = blockIdx.x * 128;

    const int tid = threadIdx.x;
    const int lane = tid & 31, wid = tid >> 5;
    const int wm = (wid & 3) * 32, wn = (wid >> 2) * 64;
    const int lrow = tid >> 2;
    const int lq   = (tid & 3) * 16;
    const int mi = lane >> 3, r8 = lane & 7;
    const uint32_t aoff = (uint32_t)((wm + (mi & 1) * 8 + r8) * 80 + ((mi >> 1) * 8) * 2);
    const uint32_t boff = (uint32_t)((wn + (mi >> 1) * 8 + r8) * 80 + ((mi & 1) * 8) * 2);

    float acc[2][8][4];
    #pragma unroll
    for (int a = 0; a < 2; a++)
        #pragma unroll
        for (int b = 0; b < 8; b++)
            #pragma unroll
            for (int d = 0; d < 4; d++) acc[a][b][d] = 0.f;

    auto load_chunk = [&](int c) {
        const uint32_t st = sb + (uint32_t)c * STG;
        const int k0 = c << 5;
        #pragma unroll
        for (int i = 0; i < 2; i++) {
            int r = lrow + i * 64;
            int gq = m0 + r; if (gq > T_ - 1) gq = T_ - 1;
            int gk = n0 + r; if (gk > T_ - 1) gk = T_ - 1;
            uint32_t d = st + (uint32_t)(r * 80) + lq;
            cp16(d,          (const char*)(qkvh + qb  + (size_t)gq * 2304 + k0) + lq);
            cp16(d + 10240u, (const char*)(qkvl + qb  + (size_t)gq * 2304 + k0) + lq);
            cp16(d + 20480u, (const char*)(qkvh + kb_ + (size_t)gk * 2304 + k0) + lq);
            cp16(d + 30720u, (const char*)(qkvl + kb_ + (size_t)gk * 2304 + k0) + lq);
        }
    };

    load_chunk(0); CP_COMMIT();
    load_chunk(1); CP_COMMIT();

    #pragma unroll
    for (int c = 0; c < 2; c++) {
        if (c == 0) { CP_WAIT(1); }
        else        { CP_WAIT(0); }
        __syncthreads();
        const uint32_t st = sb + (uint32_t)c * STG;
        #pragma unroll
        for (int kb = 0; kb < 2; kb++) {
            const uint32_t ko = (uint32_t)(kb * 32);
            uint32_t ah[2][4], al[2][4];
            ldsm4(ah[0], st + aoff + ko);
            ldsm4(ah[1], st + aoff + 1280u + ko);
            ldsm4(al[0], st + 10240u + aoff + ko);
            ldsm4(al[1], st + 10240u + aoff + 1280u + ko);
            #pragma unroll
            for (int p = 0; p < 4; p++) {
                uint32_t bh[4], bl[4];
                ldsm4(bh, st + 20480u + boff + (uint32_t)(p * 1280) + ko);
                ldsm4(bl, st + 30720u + boff + (uint32_t)(p * 1280) + ko);
                #pragma unroll
                for (int mt = 0; mt < 2; mt++) {
                    mma16816(acc[mt][2 * p],     ah[mt], bh[0], bh[1]);
                    mma16816(acc[mt][2 * p],     ah[mt], bl[0], bl[1]);
                    mma16816(acc[mt][2 * p],     al[mt], bh[0], bh[1]);
                    mma16816(acc[mt][2 * p + 1], ah[mt], bh[2], bh[3]);
                    mma16816(acc[mt][2 * p + 1], ah[mt], bl[2], bl[3]);
                    mma16816(acc[mt][2 * p + 1], al[mt], bh[2], bh[3]);
                }
            }
        }
    }

    const int g = lane >> 2, tg = lane & 3;
    #pragma unroll
    for (int mt = 0; mt < 2; mt++) {
        const int rb = m0 + wm + mt * 16 + g;
        #pragma unroll
        for (int nt = 0; nt < 8; nt++) {
            const int col = n0 + wn + nt * 8 + tg * 2;
            #pragma unroll
            for (int hh = 0; hh < 2; hh++) {
                const int row = rb + hh * 8;
                if (row < T_ && col < T_) {
                    float v0 = acc[mt][nt][hh * 2]     * 0.125f;
                    float v1 = acc[mt][nt][hh * 2 + 1] * 0.125f;
                    size_t go = (size_t)row * KPAD + col;
                    if (col + 1 < T_) *(float2*)(Cp + go) = make_float2(v0, v1);
                    else Cp[go] = v0;
                }
            }
        }
    }
}

// ---------------- softmax over HEADS -> fp16 probs (x4 vectorized) ----------------
__global__ void softmax_fp16(const float* __restrict__ dp,
                             __half* __restrict__ phi) {
    long long idx = (long long)blockIdx.x * blockDim.x + threadIdx.x;
    const long long tot = (long long)B_ * (PTT / 4);
    if (idx >= tot) return;
    const int b  = (int)(idx / (PTT / 4));
    const int r4 = (int)(idx % (PTT / 4));
    size_t base = (size_t)b * NH * PTT + (size_t)r4 * 4;
    float4 v[NH];
    float4 mx = make_float4(-1e30f, -1e30f, -1e30f, -1e30f);
    #pragma unroll
    for (int h = 0; h < NH; h++) {
        v[h] = *(const float4*)(dp + base + (size_t)h * PTT);
        mx.x = fmaxf(mx.x, v[h].x); mx.y = fmaxf(mx.y, v[h].y);
        mx.z = fmaxf(mx.z, v[h].z); mx.w = fmaxf(mx.w, v[h].w);
    }
    float4 s = make_float4(0.f, 0.f, 0.f, 0.f);
    #pragma unroll
    for (int h = 0; h < NH; h++) {
        v[h].x = expf(v[h].x - mx.x); s.x += v[h].x;
        v[h].y = expf(v[h].y - mx.y); s.y += v[h].y;
        v[h].z = expf(v[h].z - mx.z); s.z += v[h].z;
        v[h].w = expf(v[h].w - mx.w); s.w += v[h].w;
    }
    s.x = 1.f / s.x; s.y = 1.f / s.y; s.z = 1.f / s.z; s.w = 1.f / s.w;
    #pragma unroll
    for (int h = 0; h < NH; h++) {
        __half2 h0, h1;
        h0.x = __float2half(v[h].x * s.x); h0.y = __float2half(v[h].y * s.y);
        h1.x = __float2half(v[h].z * s.z); h1.y = __float2half(v[h].w * s.w);
        size_t o = base + (size_t)h * PTT;
        *(__half2*)(phi + o)     = h0;
        *(__half2*)(phi + o + 2) = h1;
    }
}

// ---------------- wa = P(fp16) @ V(fp16 split), 2 MMA passes, occ=2 ----------------
#define STGW 19456u
__global__ void __launch_bounds__(256, 2) wa_mma(
    const __half* __restrict__ phi,
    const __nv_bfloat16* __restrict__ qkvh, const __nv_bfloat16* __restrict__ qkvl,
    __nv_bfloat16* __restrict__ whi, __nv_bfloat16* __restrict__ wlo) {
    extern __shared__ __align__(128) char dsm[];
    const uint32_t sb = smem_u32(dsm);
    const int tid = threadIdx.x;
    const int lane = tid & 31, wid = tid >> 5;
    const int bh = blockIdx.y;
    const int b = bh / NH, h = bh % NH;
    const int q0 = blockIdx.x * 128;
    const int wm = (wid & 3) * 32, wn = (wid >> 2) * 32;
    const int lrow = tid >> 2;
    const int lq   = (tid & 3) * 16;
    const int mi = lane >> 3, r8 = lane & 7;
    const uint32_t aoff = (uint32_t)((wm + (mi & 1) * 8 + r8) * 80 + ((mi >> 1) * 8) * 2);
    const uint32_t voff = (uint32_t)(((mi & 1) * 8 + r8) * 144 + (wn + (mi >> 1) * 8) * 2);

    const size_t pbase = (size_t)bh * PTT;
    const __half* Vh = (const __half*)(qkvh + (size_t)b * T_ * 2304 + 1536 + h * 64);
    const __half* Vl = (const __half*)(qkvl + (size_t)b * T_ * 2304 + 1536 + h * 64);

    float acc[2][4][4];
    #pragma unroll
    for (int a = 0; a < 2; a++)
        #pragma unroll
        for (int n = 0; n < 4; n++)
            #pragma unroll
            for (int d = 0; d < 4; d++) acc[a][n][d] = 0.f;

    const int nc = (T_ + 31) / 32;  // 19

    auto load_chunk = [&](int c) {
        const uint32_t st = sb + (uint32_t)(c % 3) * STGW;
        const int k0 = c * 32;
        #pragma unroll
        for (int i = 0; i < 2; i++) {
            int r = lrow + i * 64;
            int q = q0 + r; if (q > T_ - 1) q = T_ - 1;
            int kstart = k0 + (lq >> 1);
            int nb = (T_ - kstart) * 2;
            nb = nb < 0 ? 0 : (nb > 16 ? 16 : nb);
            size_t off = pbase + (size_t)q * KPAD + k0;
            cp16z(st + (uint32_t)(r * 80) + lq, (const char*)(phi + off) + lq, nb);
        }
        {
            int vr = tid >> 3, vq = (tid & 7) * 16;
            int k = k0 + vr;
            int nb = (k < T_) ? 16 : 0;
            if (k > T_ - 1) k = T_ - 1;
            size_t off = (size_t)k * 2304;
            uint32_t d = st + 10240u + (uint32_t)(vr * 144) + vq;
            cp16z(d,         (const char*)(Vh + off) + vq, nb);
            cp16z(d + 4608u, (const char*)(Vl + off) + vq, nb);
        }
    };

    load_chunk(0); CP_COMMIT();
    load_chunk(1); CP_COMMIT();

    for (int c = 0; c < nc; c++) {
        CP_WAIT(1);
        __syncthreads();
        if (c + 2 < nc) load_chunk(c + 2);
        CP_COMMIT();
        const uint32_t st = sb + (uint32_t)(c % 3) * STGW;
        #pragma unroll
        for (int ks = 0; ks < 2; ks++) {
            const uint32_t ko = (uint32_t)(ks * 32);
            uint32_t a[2][4];
            ldsm4(a[0], st + aoff + ko);
            ldsm4(a[1], st + aoff + 1280u + ko);
            uint32_t vh0[4], vh1[4], vl0[4], vl1[4];
            const uint32_t vb = st + 10240u + voff + (uint32_t)(ks * 2304);
            ldsm4t(vh0, vb);
            ldsm4t(vh1, vb + 32u);
            ldsm4t(vl0, vb + 4608u);
            ldsm4t(vl1, vb + 4608u + 32u);
            #pragma unroll
            for (int mt = 0; mt < 2; mt++) {
                mma16816h(acc[mt][0], a[mt], vh0[0], vh0[1]);
                mma16816h(acc[mt][0], a[mt], vl0[0], vl0[1]);
                mma16816h(acc[mt][1], a[mt], vh0[2], vh0[3]);
                mma16816h(acc[mt][1], a[mt], vl0[2], vl0[3]);
                mma16816h(acc[mt][2], a[mt], vh1[0], vh1[1]);
                mma16816h(acc[mt][2], a[mt], vl1[0], vl1[1]);
                mma16816h(acc[mt][3], a[mt], vh1[2], vh1[3]);
                mma16816h(acc[mt][3], a[mt], vl1[2], vl1[3]);
            }
        }
    }

    const int g = lane >> 2, tg = lane & 3;
    #pragma unroll
    for (int mt = 0; mt < 2; mt++) {
        #pragma unroll
        for (int nt = 0; nt < 4; nt++) {
            const int col = wn + nt * 8 + tg * 2;
            #pragma unroll
            for (int hh = 0; hh < 2; hh++) {
                const int row = q0 + wm + mt * 16 + g + hh * 8;
                if (row < T_) {
                    float v0 = acc[mt][nt][hh * 2];
                    float v1 = acc[mt][nt][hh * 2 + 1];
                    size_t go = ((size_t)(b * T_ + row)) * D_ + h * 64 + col;
                    __nv_bfloat162 h2, l2;
                    h2.x = __float2bfloat16(v0); h2.y = __float2bfloat16(v1);
                    l2.x = __float2bfloat16(v0 - __bfloat162float(h2.x));
                    l2.y = __float2bfloat16(v1 - __bfloat162float(h2.y));
                    *(__nv_bfloat162*)(whi + go) = h2;
                    *(__nv_bfloat162*)(wlo + go) = l2;
                }
            }
        }
    }
}

// ---------------- host launch ----------------
extern "C" void kernel_launch(void* const* d_in, const int* in_sizes, int n_in,
                              void* d_out, int out_size) {
    const float* x      = (const float*)d_in[0];
    const float* ln1_w  = (const float*)d_in[1];
    const float* ln1_b  = (const float*)d_in[2];
    const float* qkv_w  = (const float*)d_in[3];
    const float* qkv_b  = (const float*)d_in[4];
    const float* proj_w = (const float*)d_in[5];
    const float* proj_b = (const float*)d_in[6];
    const float* ln2_w  = (const float*)d_in[7];
    const float* ln2_b  = (const float*)d_in[8];
    const float* fc1_w  = (const float*)d_in[9];
    const float* fc1_b  = (const float*)d_in[10];
    const float* fc2_w  = (const float*)d_in[11];
    const float* fc2_b  = (const float*)d_in[12];
    float* out = (float*)d_out;

    __nv_bfloat16 *yhi, *ylo, *qkh, *qkl, *wahi, *walo;
    __nv_bfloat16 *wqh, *wql, *wph, *wpl;
    __half *w1hh, *w1ll, *w2hh, *w2ll, *h16, *ph;
    float *dpb, *x1b;
    cudaGetSymbolAddress((void**)&yhi,  g_y_hi);
    cudaGetSymbolAddress((void**)&ylo,  g_y_lo);
    cudaGetSymbolAddress((void**)&qkh,  g_qkv_hi);
    cudaGetSymbolAddress((void**)&qkl,  g_qkv_lo);
    cudaGetSymbolAddress((void**)&dpb,  g_dp);
    cudaGetSymbolAddress((void**)&ph,   g_p);
    cudaGetSymbolAddress((void**)&wahi, g_wa_hi);
    cudaGetSymbolAddress((void**)&walo, g_wa_lo);
    cudaGetSymbolAddress((void**)&x1b,  g_x1);
    cudaGetSymbolAddress((void**)&h16,  g_h16);
    cudaGetSymbolAddress((void**)&wqh,  g_wq_hi);
    cudaGetSymbolAddress((void**)&wql,  g_wq_lo);
    cudaGetSymbolAddress((void**)&wph,  g_wp_hi);
    cudaGetSymbolAddress((void**)&wpl,  g_wp_lo);
    cudaGetSymbolAddress((void**)&w1hh, g_w1_hi);
    cudaGetSymbolAddress((void**)&w1ll, g_w1_lo);
    cudaGetSymbolAddress((void**)&w2hh, g_w2_hi);
    cudaGetSymbolAddress((void**)&w2ll, g_w2_lo);
    __half* y16 = (__half*)yhi;   // LN2 output reuses g_y_hi as fp16 bits

    const int SMEM_L = 3 * (int)STG3;      // 98304
    const int SMEM_H = 3 * (int)STGH;      // 73728
    const int SMEM_S = 2 * (int)STG;       // 81920
    const int SMEM_W = 3 * (int)STGW;      // 58368
    cudaFuncSetAttribute(gemm_lin<0, false, true >, cudaFuncAttributeMaxDynamicSharedMemorySize, SMEM_L);
    cudaFuncSetAttribute(gemm_lin<0, true,  false>, cudaFuncAttributeMaxDynamicSharedMemorySize, SMEM_L);
    cudaFuncSetAttribute(gemm_hs<1, false, true >, cudaFuncAttributeMaxDynamicSharedMemorySize, SMEM_H);
    cudaFuncSetAttribute(gemm_hs<0, true,  false>, cudaFuncAttributeMaxDynamicSharedMemorySize, SMEM_H);
    cudaFuncSetAttribute(scores_mma,  cudaFuncAttributeMaxDynamicSharedMemorySize, SMEM_S);
    cudaFuncSetAttribute(wa_mma,      cudaFuncAttributeMaxDynamicSharedMemorySize, SMEM_W);

    const int MT = (BT + 127) / 128;  // 145

    wconv_kernel<<<dim3(2304 / 32, 768 / 32),    dim3(32, 8)>>>(qkv_w,  wqh,  wql,  768,  2304);
    wconv_kernel<<<dim3(768 / 32,  768 / 32),    dim3(32, 8)>>>(proj_w, wph,  wpl,  768,  768);
    wconv_h_kernel<<<dim3(3072 / 32, 768 / 32),  dim3(32, 8)>>>(fc1_w,  w1hh, w1ll, 768,  3072);
    wconv_h_kernel<<<dim3(768 / 32,  3072 / 32), dim3(32, 8)>>>(fc2_w,  w2hh, w2ll, 3072, 768);

    // 1) LN1 -> bf16 split
    ln_kernel<<<BT, 256>>>(x, ln1_w, ln1_b, yhi, ylo);
    // 2) QKV projection (3-pass bf16) -> split qkv (Q,K bf16 split; V fp16 split)
    gemm_lin<0, false, true><<<dim3(2304 / 128, MT), 256, SMEM_L>>>(
        yhi, ylo, wqh, wql, qkv_b, nullptr, nullptr, qkh, qkl, BT, 2304, D_, 1536);
    // 3) scores -> fp32 dp (padded rows)
    scores_mma<<<dim3(5, 5, B_ * NH), 256, SMEM_S>>>(qkh, qkl, dpb);
    // 4) softmax over heads -> fp16 probs
    {
        long long total = (long long)B_ * (PTT / 4);
        int grid = (int)((total + 255) / 256);
        softmax_fp16<<<grid, 256>>>(dpb, ph);
    }
    // 5) wa = P(fp16) @ V(fp16 split) -> bf16 split
    wa_mma<<<dim3(5, B_ * NH), 256, SMEM_W>>>(ph, qkh, qkl, wahi, walo);
    // 6) output projection + residual (3-pass bf16)
    gemm_lin<0, true, false><<<dim3(D_ / 128, MT), 256, SMEM_L>>>(
        wahi, walo, wph, wpl, proj_b, x, x1b, nullptr, nullptr, BT, D_, D_, 1 << 30);
    // 7) LN2 -> fp16 single
    ln_fp16_kernel<<<BT, 256>>>(x1b, ln2_w, ln2_b, y16);
    // 8) fc1 + exact GELU (2-pass fp16) -> fp16 hidden
    gemm_hs<1, false, true><<<dim3(H_ / 128, MT), 256, SMEM_H>>>(
        y16, w1hh, w1ll, fc1_b, nullptr, nullptr, h16, BT, H_, D_);
    // 9) fc2 + residual (2-pass fp16) -> output
    gemm_hs<0, true, false><<<dim3(D_ / 128, MT), 256, SMEM_H>>>(
        h16, w2hh, w2ll, fc2_b, x1b, out, nullptr, BT, D_, H_);
}

// round 16
// speedup vs baseline: 1.3213x; 1.1037x over previous
#include <cuda_runtime.h>
#include <cuda_bf16.h>
#include <cuda_fp16.h>
#include <math.h>
#include <stdint.h>

#define BT   18464          // B*T
#define B_   32
#define T_   577
#define D_   768
#define H_   3072
#define NH   12
#define KPAD 584            // padded key dim for dp/probs rows (16B-aligned)
#define PTT  (T_ * KPAD)    // per-(b,h) plane size (divisible by 4)

// ---------------- static scratch (all-fp16 pipeline) ----------------
__device__ __half g_y16  [(size_t)BT * D_];      // LN outputs, fp16 single
__device__ __half g_qkv_hi[(size_t)BT * 2304];   // Q,K,V fp16 hi
__device__ __half g_qkv_lo[(size_t)BT * 2304];   // Q,K,V fp16 lo
__device__ float  g_dp   [(size_t)B_ * NH * PTT];
__device__ __half g_p    [(size_t)B_ * NH * PTT];
__device__ __half g_wa16 [(size_t)BT * D_];      // attention out, fp16 single
__device__ float  g_x1   [(size_t)BT * D_];
__device__ __half g_h16  [(size_t)BT * H_];      // MLP hidden, fp16 single
__device__ __half g_wq_hi[2304 * 768], g_wq_lo[2304 * 768];
__device__ __half g_wp_hi[ 768 * 768], g_wp_lo[ 768 * 768];
__device__ __half g_w1_hi[3072 * 768], g_w1_lo[3072 * 768];
__device__ __half g_w2_hi[ 768 * 3072], g_w2_lo[ 768 * 3072];

// ---------------- helpers ----------------
__device__ __forceinline__ uint32_t smem_u32(const void* p) {
    uint32_t a;
    asm("{ .reg .u64 t; cvta.to.shared.u64 t, %1; cvt.u32.u64 %0, t; }" : "=r"(a) : "l"(p));
    return a;
}
__device__ __forceinline__ void cp16(uint32_t dst, const void* src) {
    asm volatile("cp.async.cg.shared.global [%0], [%1], 16;" :: "r"(dst), "l"(src));
}
__device__ __forceinline__ void cp16z(uint32_t dst, const void* src, int nb) {
    asm volatile("cp.async.cg.shared.global [%0], [%1], 16, %2;" :: "r"(dst), "l"(src), "r"(nb));
}
#define CP_COMMIT() asm volatile("cp.async.commit_group;" ::: "memory")
#define CP_WAIT(n)  asm volatile("cp.async.wait_group %0;" :: "n"(n) : "memory")

__device__ __forceinline__ void ldsm4(uint32_t* r, uint32_t a) {
    asm volatile("ldmatrix.sync.aligned.m8n8.x4.shared.b16 {%0,%1,%2,%3}, [%4];"
                 : "=r"(r[0]), "=r"(r[1]), "=r"(r[2]), "=r"(r[3]) : "r"(a));
}
__device__ __forceinline__ void ldsm4t(uint32_t* r, uint32_t a) {
    asm volatile("ldmatrix.sync.aligned.m8n8.x4.trans.shared.b16 {%0,%1,%2,%3}, [%4];"
                 : "=r"(r[0]), "=r"(r[1]), "=r"(r[2]), "=r"(r[3]) : "r"(a));
}
__device__ __forceinline__ void mma16816h(float* c, const uint32_t* a, uint32_t b0, uint32_t b1) {
    asm volatile("mma.sync.aligned.m16n8k16.row.col.f32.f16.f16.f32 "
                 "{%0,%1,%2,%3}, {%4,%5,%6,%7}, {%8,%9}, {%0,%1,%2,%3};"
                 : "+f"(c[0]), "+f"(c[1]), "+f"(c[2]), "+f"(c[3])
                 : "r"(a[0]), "r"(a[1]), "r"(a[2]), "r"(a[3]), "r"(b0), "r"(b1));
}

// ---------------- weight transpose+split (fp16) ----------------
__global__ void wconv_h_kernel(const float* __restrict__ W,
                               __half* __restrict__ hi,
                               __half* __restrict__ lo, int K, int N) {
    __shared__ float t[32][33];
    const int k0 = blockIdx.y * 32, n0 = blockIdx.x * 32;
    #pragma unroll
    for (int i = 0; i < 4; i++)
        t[threadIdx.y + i * 8][threadIdx.x] =
            W[(size_t)(k0 + threadIdx.y + i * 8) * N + n0 + threadIdx.x];
    __syncthreads();
    #pragma unroll
    for (int i = 0; i < 4; i++) {
        int n = n0 + threadIdx.y + i * 8;
        int k = k0 + threadIdx.x;
        float x = t[threadIdx.x][threadIdx.y + i * 8];
        __half h = __float2half(x);
        hi[(size_t)n * K + k] = h;
        lo[(size_t)n * K + k] = __float2half(x - __half2float(h));
    }
}

// ---------------- LayerNorm -> fp16 single ----------------
__global__ void __launch_bounds__(256) ln_fp16_kernel(const float* __restrict__ x,
                                                      const float* __restrict__ w,
                                                      const float* __restrict__ b,
                                                      __half* __restrict__ y16) {
    const int row = blockIdx.x;
    const float* xr = x + (size_t)row * D_;
    const int tid = threadIdx.x;

    float v0 = xr[tid], v1 = xr[tid + 256], v2 = xr[tid + 512];
    float s  = v0 + v1 + v2;
    float s2 = v0 * v0 + v1 * v1 + v2 * v2;
    #pragma unroll
    for (int o = 16; o > 0; o >>= 1) {
        s  += __shfl_xor_sync(0xffffffffu, s,  o);
        s2 += __shfl_xor_sync(0xffffffffu, s2, o);
    }
    __shared__ float sh[8], sh2[8];
    const int wi = tid >> 5, ln = tid & 31;
    if (ln == 0) { sh[wi] = s; sh2[wi] = s2; }
    __syncthreads();
    if (wi == 0) {
        s  = (ln < 8) ? sh[ln]  : 0.f;
        s2 = (ln < 8) ? sh2[ln] : 0.f;
        #pragma unroll
        for (int o = 4; o > 0; o >>= 1) {
            s  += __shfl_xor_sync(0xffffffffu, s,  o);
            s2 += __shfl_xor_sync(0xffffffffu, s2, o);
        }
        if (ln == 0) { sh[0] = s; sh2[0] = s2; }
    }
    __syncthreads();
    const float mu  = sh[0] * (1.0f / D_);
    const float var = sh2[0] * (1.0f / D_) - mu * mu;
    const float rs  = rsqrtf(var + 1e-6f);
    size_t base = (size_t)row * D_;
    #pragma unroll
    for (int j = 0; j < 3; j++) {
        int c = tid + j * 256;
        float v = (j == 0 ? v0 : (j == 1 ? v1 : v2));
        y16[base + c] = __float2half((v - mu) * rs * w[c] + b[c]);
    }
}

// ================= 2-pass fp16 GEMM: A single fp16, W fp16 hi/lo =================
// stage: A@0 (8KB), Wh@8192, Wl@16384; stage=24576. Swizzled 64B rows, 3-stage, 1 sync/chunk.
// OMODE: 0 = fp32 C (+res), 1 = fp16 single Ch, 2 = fp16 hi/lo split (Chi, Clo)
#define STGH 24576u
template <int ACT, bool RES, int OMODE>
__global__ void __launch_bounds__(256, 2) gemm_hs(
    const __half* __restrict__ A,
    const __half* __restrict__ Whh, const __half* __restrict__ Wll,
    const float* __restrict__ bias, const float* __restrict__ res,
    float* __restrict__ C, __half* __restrict__ Chi, __half* __restrict__ Clo,
    int M, int N, int K) {
    extern __shared__ __align__(128) char dsm[];
    const uint32_t sb = smem_u32(dsm);
    const int tid = threadIdx.x;
    const int lane = tid & 31, wid = tid >> 5;
    const int m0 = blockIdx.y * 128, n0 = blockIdx.x * 128;
    const int wm = (wid & 3) * 32, wn = (wid >> 2) * 64;
    const int lrow = tid >> 2;
    const int lseg = tid & 3;
    const int mi = lane >> 3, r8 = lane & 7;
    const uint32_t xr_ = (uint32_t)((r8 >> 1) & 3);
    const int a_row = wm + (mi & 1) * 8 + r8;
    const int b_row = wn + (mi >> 1) * 8 + r8;
    const uint32_t aoff = (uint32_t)(a_row * 64) + ((((uint32_t)(mi >> 1)) ^ xr_) << 4);
    const uint32_t boff = (uint32_t)(b_row * 64) + ((((uint32_t)(mi & 1)) ^ xr_) << 4);

    float acc[2][8][4];
    #pragma unroll
    for (int a = 0; a < 2; a++)
        #pragma unroll
        for (int b = 0; b < 8; b++)
            #pragma unroll
            for (int d = 0; d < 4; d++) acc[a][b][d] = 0.f;

    const int nc = K >> 5;

    auto load_chunk = [&](int c) {
        const uint32_t st = sb + (uint32_t)(c % 3) * STGH;
        const int k0 = c << 5;
        #pragma unroll
        for (int i = 0; i < 2; i++) {
            int r = lrow + i * 64;
            uint32_t dseg = (uint32_t)lseg ^ (uint32_t)((r >> 1) & 3);
            uint32_t d = st + (uint32_t)(r * 64) + (dseg << 4);
            int gr = m0 + r; if (gr > M - 1) gr = M - 1;
            size_t gb = (size_t)(n0 + r) * K + k0;
            cp16(d,          (const char*)(A   + (size_t)gr * K + k0) + lseg * 16);
            cp16(d + 8192u,  (const char*)(Whh + gb) + lseg * 16);
            cp16(d + 16384u, (const char*)(Wll + gb) + lseg * 16);
        }
    };

    load_chunk(0); CP_COMMIT();
    if (nc > 1) load_chunk(1);
    CP_COMMIT();

    for (int c = 0; c < nc; c++) {
        CP_WAIT(1);
        __syncthreads();
        if (c + 2 < nc) load_chunk(c + 2);
        CP_COMMIT();
        const uint32_t st = sb + (uint32_t)(c % 3) * STGH;
        #pragma unroll
        for (int kb = 0; kb < 2; kb++) {
            const uint32_t kx = (uint32_t)(kb * 32);
            uint32_t a_[2][4];
            ldsm4(a_[0], (st + aoff) ^ kx);
            ldsm4(a_[1], (st + aoff + 1024u) ^ kx);
            #pragma unroll
            for (int p = 0; p < 4; p++) {
                uint32_t bh[4], bl[4];
                ldsm4(bh, (st + 8192u  + boff + (uint32_t)(p * 1024)) ^ kx);
                ldsm4(bl, (st + 16384u + boff + (uint32_t)(p * 1024)) ^ kx);
                #pragma unroll
                for (int mt = 0; mt < 2; mt++) {
                    mma16816h(acc[mt][2 * p],     a_[mt], bh[0], bh[1]);
                    mma16816h(acc[mt][2 * p],     a_[mt], bl[0], bl[1]);
                    mma16816h(acc[mt][2 * p + 1], a_[mt], bh[2], bh[3]);
                    mma16816h(acc[mt][2 * p + 1], a_[mt], bl[2], bl[3]);
                }
            }
        }
    }

    const int g = lane >> 2, tg = lane & 3;
    #pragma unroll
    for (int mt = 0; mt < 2; mt++) {
        const int rb = m0 + wm + mt * 16 + g;
        #pragma unroll
        for (int nt = 0; nt < 8; nt++) {
            const int col = n0 + wn + nt * 8 + tg * 2;
            const float bv0 = bias[col], bv1 = bias[col + 1];
            #pragma unroll
            for (int hh = 0; hh < 2; hh++) {
                const int row = rb + hh * 8;
                if (row < M) {
                    float v0 = acc[mt][nt][hh * 2]     + bv0;
                    float v1 = acc[mt][nt][hh * 2 + 1] + bv1;
                    if (ACT == 1) { v0 = v0 * normcdff(v0); v1 = v1 * normcdff(v1); }
                    size_t go = (size_t)row * N + col;
                    if (RES) {
                        float2 r2 = *(const float2*)(res + go);
                        v0 += r2.x; v1 += r2.y;
                    }
                    if (OMODE == 2) {
                        __half2 h2, l2;
                        h2.x = __float2half(v0); h2.y = __float2half(v1);
                        l2.x = __float2half(v0 - __half2float(h2.x));
                        l2.y = __float2half(v1 - __half2float(h2.y));
                        *(__half2*)(Chi + go) = h2;
                        *(__half2*)(Clo + go) = l2;
                    } else if (OMODE == 1) {
                        __half2 h2;
                        h2.x = __float2half(v0); h2.y = __float2half(v1);
                        *(__half2*)(Chi + go) = h2;
                    } else {
                        *(float2*)(C + go) = make_float2(v0, v1);
                    }
                }
            }
        }
    }
}

// ================= scores: 3-pass fp16 (Q,K fp16 hi/lo), 128x128 tile, occ=2 =================
#define STG 40960u
__global__ void __launch_bounds__(256, 2) scores_mma(
    const __half* __restrict__ qkvh, const __half* __restrict__ qkvl,
    float* __restrict__ dp) {
    extern __shared__ __align__(128) char dsm[];
    const uint32_t sb = smem_u32(dsm);
    const int bh = blockIdx.z;
    const int bb = bh / NH, h = bh % NH;
    const size_t qb = (size_t)bb * T_ * 2304 + h * 64;
    const size_t kb_ = qb + 768;
    float* Cp = dp + (size_t)bh * PTT;
    const int m0 = blockIdx.y * 128, n0 = blockIdx.x * 128;

    const int tid = threadIdx.x;
    const int lane = tid & 31, wid = tid >> 5;
    const int wm = (wid & 3) * 32, wn = (wid >> 2) * 64;
    const int lrow = tid >> 2;
    const int lq   = (tid & 3) * 16;
    const int mi = lane >> 3, r8 = lane & 7;
    const uint32_t aoff = (uint32_t)((wm + (mi & 1) * 8 + r8) * 80 + ((mi >> 1) * 8) * 2);
    const uint32_t boff = (uint32_t)((wn + (mi >> 1) * 8 + r8) * 80 + ((mi & 1) * 8) * 2);

    float acc[2][8][4];
    #pragma unroll
    for (int a = 0; a < 2; a++)
        #pragma unroll
        for (int b = 0; b < 8; b++)
            #pragma unroll
            for (int d = 0; d < 4; d++) acc[a][b][d] = 0.f;

    auto load_chunk = [&](int c) {
        const uint32_t st = sb + (uint32_t)c * STG;
        const int k0 = c << 5;
        #pragma unroll
        for (int i = 0; i < 2; i++) {
            int r = lrow + i * 64;
            int gq = m0 + r; if (gq > T_ - 1) gq = T_ - 1;
            int gk = n0 + r; if (gk > T_ - 1) gk = T_ - 1;
            uint32_t d = st + (uint32_t)(r * 80) + lq;
            cp16(d,          (const char*)(qkvh + qb  + (size_t)gq * 2304 + k0) + lq);
            cp16(d + 10240u, (const char*)(qkvl + qb  + (size_t)gq * 2304 + k0) + lq);
            cp16(d + 20480u, (const char*)(qkvh + kb_ + (size_t)gk * 2304 + k0) + lq);
            cp16(d + 30720u, (const char*)(qkvl + kb_ + (size_t)gk * 2304 + k0) + lq);
        }
    };

    load_chunk(0); CP_COMMIT();
    load_chunk(1); CP_COMMIT();

    #pragma unroll
    for (int c = 0; c < 2; c++) {
        if (c == 0) { CP_WAIT(1); }
        else        { CP_WAIT(0); }
        __syncthreads();
        const uint32_t st = sb + (uint32_t)c * STG;
        #pragma unroll
        for (int kb = 0; kb < 2; kb++) {
            const uint32_t ko = (uint32_t)(kb * 32);
            uint32_t ah[2][4], al[2][4];
            ldsm4(ah[0], st + aoff + ko);
            ldsm4(ah[1], st + aoff + 1280u + ko);
            ldsm4(al[0], st + 10240u + aoff + ko);
            ldsm4(al[1], st + 10240u + aoff + 1280u + ko);
            #pragma unroll
            for (int p = 0; p < 4; p++) {
                uint32_t bh[4], bl[4];
                ldsm4(bh, st + 20480u + boff + (uint32_t)(p * 1280) + ko);
                ldsm4(bl, st + 30720u + boff + (uint32_t)(p * 1280) + ko);
                #pragma unroll
                for (int mt = 0; mt < 2; mt++) {
                    mma16816h(acc[mt][2 * p],     ah[mt], bh[0], bh[1]);
                    mma16816h(acc[mt][2 * p],     ah[mt], bl[0], bl[1]);
                    mma16816h(acc[mt][2 * p],     al[mt], bh[0], bh[1]);
                    mma16816h(acc[mt][2 * p + 1], ah[mt], bh[2], bh[3]);
                    mma16816h(acc[mt][2 * p + 1], ah[mt], bl[2], bl[3]);
                    mma16816h(acc[mt][2 * p + 1], al[mt], bh[2], bh[3]);
                }
            }
        }
    }

    const int g = lane >> 2, tg = lane & 3;
    #pragma unroll
    for (int mt = 0; mt < 2; mt++) {
        const int rb = m0 + wm + mt * 16 + g;
        #pragma unroll
        for (int nt = 0; nt < 8; nt++) {
            const int col = n0 + wn + nt * 8 + tg * 2;
            #pragma unroll
            for (int hh = 0; hh < 2; hh++) {
                const int row = rb + hh * 8;
                if (row < T_ && col < T_) {
                    float v0 = acc[mt][nt][hh * 2]     * 0.125f;
                    float v1 = acc[mt][nt][hh * 2 + 1] * 0.125f;
                    size_t go = (size_t)row * KPAD + col;
                    if (col + 1 < T_) *(float2*)(Cp + go) = make_float2(v0, v1);
                    else Cp[go] = v0;
                }
            }
        }
    }
}

// ---------------- softmax over HEADS -> fp16 probs (x4 vectorized) ----------------
__global__ void softmax_fp16(const float* __restrict__ dp,
                             __half* __restrict__ phi) {
    long long idx = (long long)blockIdx.x * blockDim.x + threadIdx.x;
    const long long tot = (long long)B_ * (PTT / 4);
    if (idx >= tot) return;
    const int b  = (int)(idx / (PTT / 4));
    const int r4 = (int)(idx % (PTT / 4));
    size_t base = (size_t)b * NH * PTT + (size_t)r4 * 4;
    float4 v[NH];
    float4 mx = make_float4(-1e30f, -1e30f, -1e30f, -1e30f);
    #pragma unroll
    for (int h = 0; h < NH; h++) {
        v[h] = *(const float4*)(dp + base + (size_t)h * PTT);
        mx.x = fmaxf(mx.x, v[h].x); mx.y = fmaxf(mx.y, v[h].y);
        mx.z = fmaxf(mx.z, v[h].z); mx.w = fmaxf(mx.w, v[h].w);
    }
    float4 s = make_float4(0.f, 0.f, 0.f, 0.f);
    #pragma unroll
    for (int h = 0; h < NH; h++) {
        v[h].x = expf(v[h].x - mx.x); s.x += v[h].x;
        v[h].y = expf(v[h].y - mx.y); s.y += v[h].y;
        v[h].z = expf(v[h].z - mx.z); s.z += v[h].z;
        v[h].w = expf(v[h].w - mx.w); s.w += v[h].w;
    }
    s.x = 1.f / s.x; s.y = 1.f / s.y; s.z = 1.f / s.z; s.w = 1.f / s.w;
    #pragma unroll
    for (int h = 0; h < NH; h++) {
        __half2 h0, h1;
        h0.x = __float2half(v[h].x * s.x); h0.y = __float2half(v[h].y * s.y);
        h1.x = __float2half(v[h].z * s.z); h1.y = __float2half(v[h].w * s.w);
        size_t o = base + (size_t)h * PTT;
        *(__half2*)(phi + o)     = h0;
        *(__half2*)(phi + o + 2) = h1;
    }
}

// ---------------- wa = P(fp16) @ V(fp16 split), 2 MMA passes, occ=2, fp16 single out ----------------
#define STGW 19456u
__global__ void __launch_bounds__(256, 2) wa_mma(
    const __half* __restrict__ phi,
    const __half* __restrict__ qkvh, const __half* __restrict__ qkvl,
    __half* __restrict__ wa16) {
    extern __shared__ __align__(128) char dsm[];
    const uint32_t sb = smem_u32(dsm);
    const int tid = threadIdx.x;
    const int lane = tid & 31, wid = tid >> 5;
    const int bh = blockIdx.y;
    const int b = bh / NH, h = bh % NH;
    const int q0 = blockIdx.x * 128;
    const int wm = (wid & 3) * 32, wn = (wid >> 2) * 32;
    const int lrow = tid >> 2;
    const int lq   = (tid & 3) * 16;
    const int mi = lane >> 3, r8 = lane & 7;
    const uint32_t aoff = (uint32_t)((wm + (mi & 1) * 8 + r8) * 80 + ((mi >> 1) * 8) * 2);
    const uint32_t voff = (uint32_t)(((mi & 1) * 8 + r8) * 144 + (wn + (mi >> 1) * 8) * 2);

    const size_t pbase = (size_t)bh * PTT;
    const __half* Vh = qkvh + (size_t)b * T_ * 2304 + 1536 + h * 64;
    const __half* Vl = qkvl + (size_t)b * T_ * 2304 + 1536 + h * 64;

    float acc[2][4][4];
    #pragma unroll
    for (int a = 0; a < 2; a++)
        #pragma unroll
        for (int n = 0; n < 4; n++)
            #pragma unroll
            for (int d = 0; d < 4; d++) acc[a][n][d] = 0.f;

    const int nc = (T_ + 31) / 32;  // 19

    auto load_chunk = [&](int c) {
        const uint32_t st = sb + (uint32_t)(c % 3) * STGW;
        const int k0 = c * 32;
        #pragma unroll
        for (int i = 0; i < 2; i++) {
            int r = lrow + i * 64;
            int q = q0 + r; if (q > T_ - 1) q = T_ - 1;
            int kstart = k0 + (lq >> 1);
            int nb = (T_ - kstart) * 2;
            nb = nb < 0 ? 0 : (nb > 16 ? 16 : nb);
            size_t off = pbase + (size_t)q * KPAD + k0;
            cp16z(st + (uint32_t)(r * 80) + lq, (const char*)(phi + off) + lq, nb);
        }
        {
            int vr = tid >> 3, vq = (tid & 7) * 16;
            int k = k0 + vr;
            int nb = (k < T_) ? 16 : 0;
            if (k > T_ - 1) k = T_ - 1;
            size_t off = (size_t)k * 2304;
            uint32_t d = st + 10240u + (uint32_t)(vr * 144) + vq;
            cp16z(d,         (const char*)(Vh + off) + vq, nb);
            cp16z(d + 4608u, (const char*)(Vl + off) + vq, nb);
        }
    };

    load_chunk(0); CP_COMMIT();
    load_chunk(1); CP_COMMIT();

    for (int c = 0; c < nc; c++) {
        CP_WAIT(1);
        __syncthreads();
        if (c + 2 < nc) load_chunk(c + 2);
        CP_COMMIT();
        const uint32_t st = sb + (uint32_t)(c % 3) * STGW;
        #pragma unroll
        for (int ks = 0; ks < 2; ks++) {
            const uint32_t ko = (uint32_t)(ks * 32);
            uint32_t a[2][4];
            ldsm4(a[0], st + aoff + ko);
            ldsm4(a[1], st + aoff + 1280u + ko);
            uint32_t vh0[4], vh1[4], vl0[4], vl1[4];
            const uint32_t vb = st + 10240u + voff + (uint32_t)(ks * 2304);
            ldsm4t(vh0, vb);
            ldsm4t(vh1, vb + 32u);
            ldsm4t(vl0, vb + 4608u);
            ldsm4t(vl1, vb + 4608u + 32u);
            #pragma unroll
            for (int mt = 0; mt < 2; mt++) {
                mma16816h(acc[mt][0], a[mt], vh0[0], vh0[1]);
                mma16816h(acc[mt][0], a[mt], vl0[0], vl0[1]);
                mma16816h(acc[mt][1], a[mt], vh0[2], vh0[3]);
                mma16816h(acc[mt][1], a[mt], vl0[2], vl0[3]);
                mma16816h(acc[mt][2], a[mt], vh1[0], vh1[1]);
                mma16816h(acc[mt][2], a[mt], vl1[0], vl1[1]);
                mma16816h(acc[mt][3], a[mt], vh1[2], vh1[3]);
                mma16816h(acc[mt][3], a[mt], vl1[2], vl1[3]);
            }
        }
    }

    const int g = lane >> 2, tg = lane & 3;
    #pragma unroll
    for (int mt = 0; mt < 2; mt++) {
        #pragma unroll
        for (int nt = 0; nt < 4; nt++) {
            const int col = wn + nt * 8 + tg * 2;
            #pragma unroll
            for (int hh = 0; hh < 2; hh++) {
                const int row = q0 + wm + mt * 16 + g + hh * 8;
                if (row < T_) {
                    __half2 h2;
                    h2.x = __float2half(acc[mt][nt][hh * 2]);
                    h2.y = __float2half(acc[mt][nt][hh * 2 + 1]);
                    size_t go = ((size_t)(b * T_ + row)) * D_ + h * 64 + col;
                    *(__half2*)(wa16 + go) = h2;
                }
            }
        }
    }
}

// ---------------- host launch ----------------
extern "C" void kernel_launch(void* const* d_in, const int* in_sizes, int n_in,
                              void* d_out, int out_size) {
    const float* x      = (const float*)d_in[0];
    const float* ln1_w  = (const float*)d_in[1];
    const float* ln1_b  = (const float*)d_in[2];
    const float* qkv_w  = (const float*)d_in[3];
    const float* qkv_b  = (const float*)d_in[4];
    const float* proj_w = (const float*)d_in[5];
    const float* proj_b = (const float*)d_in[6];
    const float* ln2_w  = (const float*)d_in[7];
    const float* ln2_b  = (const float*)d_in[8];
    const float* fc1_w  = (const float*)d_in[9];
    const float* fc1_b  = (const float*)d_in[10];
    const float* fc2_w  = (const float*)d_in[11];
    const float* fc2_b  = (const float*)d_in[12];
    float* out = (float*)d_out;

    __half *y16, *qkh, *qkl, *wa16, *h16, *ph;
    __half *wqh, *wql, *wph, *wpl, *w1hh, *w1ll, *w2hh, *w2ll;
    float *dpb, *x1b;
    cudaGetSymbolAddress((void**)&y16,  g_y16);
    cudaGetSymbolAddress((void**)&qkh,  g_qkv_hi);
    cudaGetSymbolAddress((void**)&qkl,  g_qkv_lo);
    cudaGetSymbolAddress((void**)&dpb,  g_dp);
    cudaGetSymbolAddress((void**)&ph,   g_p);
    cudaGetSymbolAddress((void**)&wa16, g_wa16);
    cudaGetSymbolAddress((void**)&x1b,  g_x1);
    cudaGetSymbolAddress((void**)&h16,  g_h16);
    cudaGetSymbolAddress((void**)&wqh,  g_wq_hi);
    cudaGetSymbolAddress((void**)&wql,  g_wq_lo);
    cudaGetSymbolAddress((void**)&wph,  g_wp_hi);
    cudaGetSymbolAddress((void**)&wpl,  g_wp_lo);
    cudaGetSymbolAddress((void**)&w1hh, g_w1_hi);
    cudaGetSymbolAddress((void**)&w1ll, g_w1_lo);
    cudaGetSymbolAddress((void**)&w2hh, g_w2_hi);
    cudaGetSymbolAddress((void**)&w2ll, g_w2_lo);

    const int SMEM_H = 3 * (int)STGH;      // 73728
    const int SMEM_S = 2 * (int)STG;       // 81920
    const int SMEM_W = 3 * (int)STGW;      // 58368
    cudaFuncSetAttribute(gemm_hs<0, false, 2>, cudaFuncAttributeMaxDynamicSharedMemorySize, SMEM_H);
    cudaFuncSetAttribute(gemm_hs<0, true,  0>, cudaFuncAttributeMaxDynamicSharedMemorySize, SMEM_H);
    cudaFuncSetAttribute(gemm_hs<1, false, 1>, cudaFuncAttributeMaxDynamicSharedMemorySize, SMEM_H);
    cudaFuncSetAttribute(scores_mma,  cudaFuncAttributeMaxDynamicSharedMemorySize, SMEM_S);
    cudaFuncSetAttribute(wa_mma,      cudaFuncAttributeMaxDynamicSharedMemorySize, SMEM_W);

    const int MT = (BT + 127) / 128;  // 145

    wconv_h_kernel<<<dim3(2304 / 32, 768 / 32),  dim3(32, 8)>>>(qkv_w,  wqh,  wql,  768,  2304);
    wconv_h_kernel<<<dim3(768 / 32,  768 / 32),  dim3(32, 8)>>>(proj_w, wph,  wpl,  768,  768);
    wconv_h_kernel<<<dim3(3072 / 32, 768 / 32),  dim3(32, 8)>>>(fc1_w,  w1hh, w1ll, 768,  3072);
    wconv_h_kernel<<<dim3(768 / 32,  3072 / 32), dim3(32, 8)>>>(fc2_w,  w2hh, w2ll, 3072, 768);

    // 1) LN1 -> fp16 single
    ln_fp16_kernel<<<BT, 256>>>(x, ln1_w, ln1_b, y16);
    // 2) QKV projection (2-pass fp16) -> Q,K,V fp16 hi/lo split
    gemm_hs<0, false, 2><<<dim3(2304 / 128, MT), 256, SMEM_H>>>(
        y16, wqh, wql, qkv_b, nullptr, nullptr, qkh, qkl, BT, 2304, D_);
    // 3) scores (3-pass fp16, Q/K 22-bit effective) -> fp32 dp
    scores_mma<<<dim3(5, 5, B_ * NH), 256, SMEM_S>>>(qkh, qkl, dpb);
    // 4) softmax over heads -> fp16 probs
    {
        long long total = (long long)B_ * (PTT / 4);
        int grid = (int)((total + 255) / 256);
        softmax_fp16<<<grid, 256>>>(dpb, ph);
    }
    // 5) wa = P @ V -> fp16 single
    wa_mma<<<dim3(5, B_ * NH), 256, SMEM_W>>>(ph, qkh, qkl, wa16);
    // 6) output projection + residual (2-pass fp16) -> fp32 x1
    gemm_hs<0, true, 0><<<dim3(D_ / 128, MT), 256, SMEM_H>>>(
        wa16, wph, wpl, proj_b, x, x1b, nullptr, nullptr, BT, D_, D_);
    // 7) LN2 -> fp16 single
    ln_fp16_kernel<<<BT, 256>>>(x1b, ln2_w, ln2_b, y16);
    // 8) fc1 + exact GELU (2-pass fp16) -> fp16 hidden
    gemm_hs<1, false, 1><<<dim3(H_ / 128, MT), 256, SMEM_H>>>(
        y16, w1hh, w1ll, fc1_b, nullptr, nullptr, h16, nullptr, BT, H_, D_);
    // 9) fc2 + residual (2-pass fp16) -> output
    gemm_hs<0, true, 0><<<dim3(D_ / 128, MT), 256, SMEM_H>>>(
        h16, w2hh, w2ll, fc2_b, x1b, out, nullptr, nullptr, BT, D_, H_);
}

// round 17
// speedup vs baseline: 1.3442x; 1.0174x over previous
#include <cuda_runtime.h>
#include <cuda_bf16.h>
#include <cuda_fp16.h>
#include <math.h>
#include <stdint.h>

#define BT   18464          // B*T
#define B_   32
#define T_   577
#define D_   768
#define H_   3072
#define NH   12
#define KPAD 584            // padded key dim for dp/probs rows (16B-aligned)
#define PTT  (T_ * KPAD)    // per-(b,h) plane size (divisible by 4)

// ---------------- static scratch (all-fp16 pipeline) ----------------
__device__ __half g_y16  [(size_t)BT * D_];      // LN outputs, fp16 single
__device__ __half g_qkv_hi[(size_t)BT * 2304];   // Q,K,V fp16 hi
__device__ __half g_qkv_lo[(size_t)BT * 2304];   // Q,K,V fp16 lo
__device__ __half g_dp16 [(size_t)B_ * NH * PTT];  // scores, fp16
__device__ __half g_p    [(size_t)B_ * NH * PTT];
__device__ __half g_wa16 [(size_t)BT * D_];      // attention out, fp16 single
__device__ float  g_x1   [(size_t)BT * D_];
__device__ __half g_h16  [(size_t)BT * H_];      // MLP hidden, fp16 single
__device__ __half g_wq_hi[2304 * 768], g_wq_lo[2304 * 768];
__device__ __half g_wp_hi[ 768 * 768], g_wp_lo[ 768 * 768];
__device__ __half g_w1_hi[3072 * 768], g_w1_lo[3072 * 768];
__device__ __half g_w2_hi[ 768 * 3072], g_w2_lo[ 768 * 3072];

// ---------------- helpers ----------------
__device__ __forceinline__ uint32_t smem_u32(const void* p) {
    uint32_t a;
    asm("{ .reg .u64 t; cvta.to.shared.u64 t, %1; cvt.u32.u64 %0, t; }" : "=r"(a) : "l"(p));
    return a;
}
__device__ __forceinline__ void cp16(uint32_t dst, const void* src) {
    asm volatile("cp.async.cg.shared.global [%0], [%1], 16;" :: "r"(dst), "l"(src));
}
__device__ __forceinline__ void cp16z(uint32_t dst, const void* src, int nb) {
    asm volatile("cp.async.cg.shared.global [%0], [%1], 16, %2;" :: "r"(dst), "l"(src), "r"(nb));
}
#define CP_COMMIT() asm volatile("cp.async.commit_group;" ::: "memory")
#define CP_WAIT(n)  asm volatile("cp.async.wait_group %0;" :: "n"(n) : "memory")

__device__ __forceinline__ void ldsm4(uint32_t* r, uint32_t a) {
    asm volatile("ldmatrix.sync.aligned.m8n8.x4.shared.b16 {%0,%1,%2,%3}, [%4];"
                 : "=r"(r[0]), "=r"(r[1]), "=r"(r[2]), "=r"(r[3]) : "r"(a));
}
__device__ __forceinline__ void ldsm4t(uint32_t* r, uint32_t a) {
    asm volatile("ldmatrix.sync.aligned.m8n8.x4.trans.shared.b16 {%0,%1,%2,%3}, [%4];"
                 : "=r"(r[0]), "=r"(r[1]), "=r"(r[2]), "=r"(r[3]) : "r"(a));
}
__device__ __forceinline__ void mma16816h(float* c, const uint32_t* a, uint32_t b0, uint32_t b1) {
    asm volatile("mma.sync.aligned.m16n8k16.row.col.f32.f16.f16.f32 "
                 "{%0,%1,%2,%3}, {%4,%5,%6,%7}, {%8,%9}, {%0,%1,%2,%3};"
                 : "+f"(c[0]), "+f"(c[1]), "+f"(c[2]), "+f"(c[3])
                 : "r"(a[0]), "r"(a[1]), "r"(a[2]), "r"(a[3]), "r"(b0), "r"(b1));
}

// ---------------- weight transpose+split (fp16) ----------------
__global__ void wconv_h_kernel(const float* __restrict__ W,
                               __half* __restrict__ hi,
                               __half* __restrict__ lo, int K, int N) {
    __shared__ float t[32][33];
    const int k0 = blockIdx.y * 32, n0 = blockIdx.x * 32;
    #pragma unroll
    for (int i = 0; i < 4; i++)
        t[threadIdx.y + i * 8][threadIdx.x] =
            W[(size_t)(k0 + threadIdx.y + i * 8) * N + n0 + threadIdx.x];
    __syncthreads();
    #pragma unroll
    for (int i = 0; i < 4; i++) {
        int n = n0 + threadIdx.y + i * 8;
        int k = k0 + threadIdx.x;
        float x = t[threadIdx.x][threadIdx.y + i * 8];
        __half h = __float2half(x);
        hi[(size_t)n * K + k] = h;
        lo[(size_t)n * K + k] = __float2half(x - __half2float(h));
    }
}

// ---------------- LayerNorm -> fp16 single ----------------
__global__ void __launch_bounds__(256) ln_fp16_kernel(const float* __restrict__ x,
                                                      const float* __restrict__ w,
                                                      const float* __restrict__ b,
                                                      __half* __restrict__ y16) {
    const int row = blockIdx.x;
    const float* xr = x + (size_t)row * D_;
    const int tid = threadIdx.x;

    float v0 = xr[tid], v1 = xr[tid + 256], v2 = xr[tid + 512];
    float s  = v0 + v1 + v2;
    float s2 = v0 * v0 + v1 * v1 + v2 * v2;
    #pragma unroll
    for (int o = 16; o > 0; o >>= 1) {
        s  += __shfl_xor_sync(0xffffffffu, s,  o);
        s2 += __shfl_xor_sync(0xffffffffu, s2, o);
    }
    __shared__ float sh[8], sh2[8];
    const int wi = tid >> 5, ln = tid & 31;
    if (ln == 0) { sh[wi] = s; sh2[wi] = s2; }
    __syncthreads();
    if (wi == 0) {
        s  = (ln < 8) ? sh[ln]  : 0.f;
        s2 = (ln < 8) ? sh2[ln] : 0.f;
        #pragma unroll
        for (int o = 4; o > 0; o >>= 1) {
            s  += __shfl_xor_sync(0xffffffffu, s,  o);
            s2 += __shfl_xor_sync(0xffffffffu, s2, o);
        }
        if (ln == 0) { sh[0] = s; sh2[0] = s2; }
    }
    __syncthreads();
    const float mu  = sh[0] * (1.0f / D_);
    const float var = sh2[0] * (1.0f / D_) - mu * mu;
    const float rs  = rsqrtf(var + 1e-6f);
    size_t base = (size_t)row * D_;
    #pragma unroll
    for (int j = 0; j < 3; j++) {
        int c = tid + j * 256;
        float v = (j == 0 ? v0 : (j == 1 ? v1 : v2));
        y16[base + c] = __float2half((v - mu) * rs * w[c] + b[c]);
    }
}

// ================= 2-pass fp16 GEMM: A single fp16, W fp16 hi/lo =================
// stage: A@0 (8KB), Wh@8192, Wl@16384; stage=24576. Swizzled 64B rows, 3-stage, 1 sync/chunk.
// OMODE: 0 = fp32 C (+res), 1 = fp16 single Ch, 2 = fp16 hi/lo split (Chi, Clo)
#define STGH 24576u
template <int ACT, bool RES, int OMODE>
__global__ void __launch_bounds__(256, 2) gemm_hs(
    const __half* __restrict__ A,
    const __half* __restrict__ Whh, const __half* __restrict__ Wll,
    const float* __restrict__ bias, const float* __restrict__ res,
    float* __restrict__ C, __half* __restrict__ Chi, __half* __restrict__ Clo,
    int M, int N, int K) {
    extern __shared__ __align__(128) char dsm[];
    const uint32_t sb = smem_u32(dsm);
    const int tid = threadIdx.x;
    const int lane = tid & 31, wid = tid >> 5;
    const int m0 = blockIdx.y * 128, n0 = blockIdx.x * 128;
    const int wm = (wid & 3) * 32, wn = (wid >> 2) * 64;
    const int lrow = tid >> 2;
    const int lseg = tid & 3;
    const int mi = lane >> 3, r8 = lane & 7;
    const uint32_t xr_ = (uint32_t)((r8 >> 1) & 3);
    const int a_row = wm + (mi & 1) * 8 + r8;
    const int b_row = wn + (mi >> 1) * 8 + r8;
    const uint32_t aoff = (uint32_t)(a_row * 64) + ((((uint32_t)(mi >> 1)) ^ xr_) << 4);
    const uint32_t boff = (uint32_t)(b_row * 64) + ((((uint32_t)(mi & 1)) ^ xr_) << 4);

    float acc[2][8][4];
    #pragma unroll
    for (int a = 0; a < 2; a++)
        #pragma unroll
        for (int b = 0; b < 8; b++)
            #pragma unroll
            for (int d = 0; d < 4; d++) acc[a][b][d] = 0.f;

    const int nc = K >> 5;

    auto load_chunk = [&](int c) {
        const uint32_t st = sb + (uint32_t)(c % 3) * STGH;
        const int k0 = c << 5;
        #pragma unroll
        for (int i = 0; i < 2; i++) {
            int r = lrow + i * 64;
            uint32_t dseg = (uint32_t)lseg ^ (uint32_t)((r >> 1) & 3);
            uint32_t d = st + (uint32_t)(r * 64) + (dseg << 4);
            int gr = m0 + r; if (gr > M - 1) gr = M - 1;
            size_t gb = (size_t)(n0 + r) * K + k0;
            cp16(d,          (const char*)(A   + (size_t)gr * K + k0) + lseg * 16);
            cp16(d + 8192u,  (const char*)(Whh + gb) + lseg * 16);
            cp16(d + 16384u, (const char*)(Wll + gb) + lseg * 16);
        }
    };

    load_chunk(0); CP_COMMIT();
    if (nc > 1) load_chunk(1);
    CP_COMMIT();

    for (int c = 0; c < nc; c++) {
        CP_WAIT(1);
        __syncthreads();
        if (c + 2 < nc) load_chunk(c + 2);
        CP_COMMIT();
        const uint32_t st = sb + (uint32_t)(c % 3) * STGH;
        #pragma unroll
        for (int kb = 0; kb < 2; kb++) {
            const uint32_t kx = (uint32_t)(kb * 32);
            uint32_t a_[2][4];
            ldsm4(a_[0], (st + aoff) ^ kx);
            ldsm4(a_[1], (st + aoff + 1024u) ^ kx);
            #pragma unroll
            for (int p = 0; p < 4; p++) {
                uint32_t bh[4], bl[4];
                ldsm4(bh, (st + 8192u  + boff + (uint32_t)(p * 1024)) ^ kx);
                ldsm4(bl, (st + 16384u + boff + (uint32_t)(p * 1024)) ^ kx);
                #pragma unroll
                for (int mt = 0; mt < 2; mt++) {
                    mma16816h(acc[mt][2 * p],     a_[mt], bh[0], bh[1]);
                    mma16816h(acc[mt][2 * p],     a_[mt], bl[0], bl[1]);
                    mma16816h(acc[mt][2 * p + 1], a_[mt], bh[2], bh[3]);
                    mma16816h(acc[mt][2 * p + 1], a_[mt], bl[2], bl[3]);
                }
            }
        }
    }

    const int g = lane >> 2, tg = lane & 3;
    #pragma unroll
    for (int mt = 0; mt < 2; mt++) {
        const int rb = m0 + wm + mt * 16 + g;
        #pragma unroll
        for (int nt = 0; nt < 8; nt++) {
            const int col = n0 + wn + nt * 8 + tg * 2;
            const float bv0 = bias[col], bv1 = bias[col + 1];
            #pragma unroll
            for (int hh = 0; hh < 2; hh++) {
                const int row = rb + hh * 8;
                if (row < M) {
                    float v0 = acc[mt][nt][hh * 2]     + bv0;
                    float v1 = acc[mt][nt][hh * 2 + 1] + bv1;
                    if (ACT == 1) { v0 = v0 * normcdff(v0); v1 = v1 * normcdff(v1); }
                    size_t go = (size_t)row * N + col;
                    if (RES) {
                        float2 r2 = *(const float2*)(res + go);
                        v0 += r2.x; v1 += r2.y;
                    }
                    if (OMODE == 2) {
                        __half2 h2, l2;
                        h2.x = __float2half(v0); h2.y = __float2half(v1);
                        l2.x = __float2half(v0 - __half2float(h2.x));
                        l2.y = __float2half(v1 - __half2float(h2.y));
                        *(__half2*)(Chi + go) = h2;
                        *(__half2*)(Clo + go) = l2;
                    } else if (OMODE == 1) {
                        __half2 h2;
                        h2.x = __float2half(v0); h2.y = __float2half(v1);
                        *(__half2*)(Chi + go) = h2;
                    } else {
                        *(float2*)(C + go) = make_float2(v0, v1);
                    }
                }
            }
        }
    }
}

// ================= scores: 3-pass fp16 (Q,K fp16 hi/lo), 128x128 tile, occ=2, fp16 dp out =================
#define STG 40960u
__global__ void __launch_bounds__(256, 2) scores_mma(
    const __half* __restrict__ qkvh, const __half* __restrict__ qkvl,
    __half* __restrict__ dp) {
    extern __shared__ __align__(128) char dsm[];
    const uint32_t sb = smem_u32(dsm);
    const int bh = blockIdx.z;
    const int bb = bh / NH, h = bh % NH;
    const size_t qb = (size_t)bb * T_ * 2304 + h * 64;
    const size_t kb_ = qb + 768;
    __half* Cp = dp + (size_t)bh * PTT;
    const int m0 = blockIdx.y * 128, n0 = blockIdx.x * 128;

    const int tid = threadIdx.x;
    const int lane = tid & 31, wid = tid >> 5;
    const int wm = (wid & 3) * 32, wn = (wid >> 2) * 64;
    const int lrow = tid >> 2;
    const int lq   = (tid & 3) * 16;
    const int mi = lane >> 3, r8 = lane & 7;
    const uint32_t aoff = (uint32_t)((wm + (mi & 1) * 8 + r8) * 80 + ((mi >> 1) * 8) * 2);
    const uint32_t boff = (uint32_t)((wn + (mi >> 1) * 8 + r8) * 80 + ((mi & 1) * 8) * 2);

    float acc[2][8][4];
    #pragma unroll
    for (int a = 0; a < 2; a++)
        #pragma unroll
        for (int b = 0; b < 8; b++)
            #pragma unroll
            for (int d = 0; d < 4; d++) acc[a][b][d] = 0.f;

    auto load_chunk = [&](int c) {
        const uint32_t st = sb + (uint32_t)c * STG;
        const int k0 = c << 5;
        #pragma unroll
        for (int i = 0; i < 2; i++) {
            int r = lrow + i * 64;
            int gq = m0 + r; if (gq > T_ - 1) gq = T_ - 1;
            int gk = n0 + r; if (gk > T_ - 1) gk = T_ - 1;
            uint32_t d = st + (uint32_t)(r * 80) + lq;
            cp16(d,          (const char*)(qkvh + qb  + (size_t)gq * 2304 + k0) + lq);
            cp16(d + 10240u, (const char*)(qkvl + qb  + (size_t)gq * 2304 + k0) + lq);
            cp16(d + 20480u, (const char*)(qkvh + kb_ + (size_t)gk * 2304 + k0) + lq);
            cp16(d + 30720u, (const char*)(qkvl + kb_ + (size_t)gk * 2304 + k0) + lq);
        }
    };

    load_chunk(0); CP_COMMIT();
    load_chunk(1); CP_COMMIT();

    #pragma unroll
    for (int c = 0; c < 2; c++) {
        if (c == 0) { CP_WAIT(1); }
        else        { CP_WAIT(0); }
        __syncthreads();
        const uint32_t st = sb + (uint32_t)c * STG;
        #pragma unroll
        for (int kb = 0; kb < 2; kb++) {
            const uint32_t ko = (uint32_t)(kb * 32);
            uint32_t ah[2][4], al[2][4];
            ldsm4(ah[0], st + aoff + ko);
            ldsm4(ah[1], st + aoff + 1280u + ko);
            ldsm4(al[0], st + 10240u + aoff + ko);
            ldsm4(al[1], st + 10240u + aoff + 1280u + ko);
            #pragma unroll
            for (int p = 0; p < 4; p++) {
                uint32_t bh[4], bl[4];
                ldsm4(bh, st + 20480u + boff + (uint32_t)(p * 1280) + ko);
                ldsm4(bl, st + 30720u + boff + (uint32_t)(p * 1280) + ko);
                #pragma unroll
                for (int mt = 0; mt < 2; mt++) {
                    mma16816h(acc[mt][2 * p],     ah[mt], bh[0], bh[1]);
                    mma16816h(acc[mt][2 * p],     ah[mt], bl[0], bl[1]);
                    mma16816h(acc[mt][2 * p],     al[mt], bh[0], bh[1]);
                    mma16816h(acc[mt][2 * p + 1], ah[mt], bh[2], bh[3]);
                    mma16816h(acc[mt][2 * p + 1], ah[mt], bl[2], bl[3]);
                    mma16816h(acc[mt][2 * p + 1], al[mt], bh[2], bh[3]);
                }
            }
        }
    }

    const int g = lane >> 2, tg = lane & 3;
    #pragma unroll
    for (int mt = 0; mt < 2; mt++) {
        const int rb = m0 + wm + mt * 16 + g;
        #pragma unroll
        for (int nt = 0; nt < 8; nt++) {
            const int col = n0 + wn + nt * 8 + tg * 2;
            #pragma unroll
            for (int hh = 0; hh < 2; hh++) {
                const int row = rb + hh * 8;
                if (row < T_ && col < T_) {
                    __half2 h2;
                    h2.x = __float2half(acc[mt][nt][hh * 2]     * 0.125f);
                    h2.y = __float2half(acc[mt][nt][hh * 2 + 1] * 0.125f);
                    size_t go = (size_t)row * KPAD + col;
                    if (col + 1 < T_) *(__half2*)(Cp + go) = h2;
                    else Cp[go] = h2.x;
                }
            }
        }
    }
}

// ---------------- softmax over HEADS (fp16 dp in) -> fp16 probs (x4 vectorized) ----------------
__global__ void softmax_fp16(const __half* __restrict__ dp,
                             __half* __restrict__ phi) {
    long long idx = (long long)blockIdx.x * blockDim.x + threadIdx.x;
    const long long tot = (long long)B_ * (PTT / 4);
    if (idx >= tot) return;
    const int b  = (int)(idx / (PTT / 4));
    const int r4 = (int)(idx % (PTT / 4));
    size_t base = (size_t)b * NH * PTT + (size_t)r4 * 4;
    float4 v[NH];
    float4 mx = make_float4(-1e30f, -1e30f, -1e30f, -1e30f);
    #pragma unroll
    for (int h = 0; h < NH; h++) {
        __half2 a = *(const __half2*)(dp + base + (size_t)h * PTT);
        __half2 c = *(const __half2*)(dp + base + (size_t)h * PTT + 2);
        v[h].x = __half2float(a.x); v[h].y = __half2float(a.y);
        v[h].z = __half2float(c.x); v[h].w = __half2float(c.y);
        mx.x = fmaxf(mx.x, v[h].x); mx.y = fmaxf(mx.y, v[h].y);
        mx.z = fmaxf(mx.z, v[h].z); mx.w = fmaxf(mx.w, v[h].w);
    }
    float4 s = make_float4(0.f, 0.f, 0.f, 0.f);
    #pragma unroll
    for (int h = 0; h < NH; h++) {
        v[h].x = expf(v[h].x - mx.x); s.x += v[h].x;
        v[h].y = expf(v[h].y - mx.y); s.y += v[h].y;
        v[h].z = expf(v[h].z - mx.z); s.z += v[h].z;
        v[h].w = expf(v[h].w - mx.w); s.w += v[h].w;
    }
    s.x = 1.f / s.x; s.y = 1.f / s.y; s.z = 1.f / s.z; s.w = 1.f / s.w;
    #pragma unroll
    for (int h = 0; h < NH; h++) {
        __half2 h0, h1;
        h0.x = __float2half(v[h].x * s.x); h0.y = __float2half(v[h].y * s.y);
        h1.x = __float2half(v[h].z * s.z); h1.y = __float2half(v[h].w * s.w);
        size_t o = base + (size_t)h * PTT;
        *(__half2*)(phi + o)     = h0;
        *(__half2*)(phi + o + 2) = h1;
    }
}

// ---------------- wa = P(fp16) @ V(fp16 split), 2 MMA passes, occ=2, fp16 single out ----------------
#define STGW 19456u
__global__ void __launch_bounds__(256, 2) wa_mma(
    const __half* __restrict__ phi,
    const __half* __restrict__ qkvh, const __half* __restrict__ qkvl,
    __half* __restrict__ wa16) {
    extern __shared__ __align__(128) char dsm[];
    const uint32_t sb = smem_u32(dsm);
    const int tid = threadIdx.x;
    const int lane = tid & 31, wid = tid >> 5;
    const int bh = blockIdx.y;
    const int b = bh / NH, h = bh % NH;
    const int q0 = blockIdx.x * 128;
    const int wm = (wid & 3) * 32, wn = (wid >> 2) * 32;
    const int lrow = tid >> 2;
    const int lq   = (tid & 3) * 16;
    const int mi = lane >> 3, r8 = lane & 7;
    const uint32_t aoff = (uint32_t)((wm + (mi & 1) * 8 + r8) * 80 + ((mi >> 1) * 8) * 2);
    const uint32_t voff = (uint32_t)(((mi & 1) * 8 + r8) * 144 + (wn + (mi >> 1) * 8) * 2);

    const size_t pbase = (size_t)bh * PTT;
    const __half* Vh = qkvh + (size_t)b * T_ * 2304 + 1536 + h * 64;
    const __half* Vl = qkvl + (size_t)b * T_ * 2304 + 1536 + h * 64;

    float acc[2][4][4];
    #pragma unroll
    for (int a = 0; a < 2; a++)
        #pragma unroll
        for (int n = 0; n < 4; n++)
            #pragma unroll
            for (int d = 0; d < 4; d++) acc[a][n][d] = 0.f;

    const int nc = (T_ + 31) / 32;  // 19

    auto load_chunk = [&](int c) {
        const uint32_t st = sb + (uint32_t)(c % 3) * STGW;
        const int k0 = c * 32;
        #pragma unroll
        for (int i = 0; i < 2; i++) {
            int r = lrow + i * 64;
            int q = q0 + r; if (q > T_ - 1) q = T_ - 1;
            int kstart = k0 + (lq >> 1);
            int nb = (T_ - kstart) * 2;
            nb = nb < 0 ? 0 : (nb > 16 ? 16 : nb);
            size_t off = pbase + (size_t)q * KPAD + k0;
            cp16z(st + (uint32_t)(r * 80) + lq, (const char*)(phi + off) + lq, nb);
        }
        {
            int vr = tid >> 3, vq = (tid & 7) * 16;
            int k = k0 + vr;
            int nb = (k < T_) ? 16 : 0;
            if (k > T_ - 1) k = T_ - 1;
            size_t off = (size_t)k * 2304;
            uint32_t d = st + 10240u + (uint32_t)(vr * 144) + vq;
            cp16z(d,         (const char*)(Vh + off) + vq, nb);
            cp16z(d + 4608u, (const char*)(Vl + off) + vq, nb);
        }
    };

    load_chunk(0); CP_COMMIT();
    load_chunk(1); CP_COMMIT();

    for (int c = 0; c < nc; c++) {
        CP_WAIT(1);
        __syncthreads();
        if (c + 2 < nc) load_chunk(c + 2);
        CP_COMMIT();
        const uint32_t st = sb + (uint32_t)(c % 3) * STGW;
        #pragma unroll
        for (int ks = 0; ks < 2; ks++) {
            const uint32_t ko = (uint32_t)(ks * 32);
            uint32_t a[2][4];
            ldsm4(a[0], st + aoff + ko);
            ldsm4(a[1], st + aoff + 1280u + ko);
            uint32_t vh0[4], vh1[4], vl0[4], vl1[4];
            const uint32_t vb = st + 10240u + voff + (uint32_t)(ks * 2304);
            ldsm4t(vh0, vb);
            ldsm4t(vh1, vb + 32u);
            ldsm4t(vl0, vb + 4608u);
            ldsm4t(vl1, vb + 4608u + 32u);
            #pragma unroll
            for (int mt = 0; mt < 2; mt++) {
                mma16816h(acc[mt][0], a[mt], vh0[0], vh0[1]);
                mma16816h(acc[mt][0], a[mt], vl0[0], vl0[1]);
                mma16816h(acc[mt][1], a[mt], vh0[2], vh0[3]);
                mma16816h(acc[mt][1], a[mt], vl0[2], vl0[3]);
                mma16816h(acc[mt][2], a[mt], vh1[0], vh1[1]);
                mma16816h(acc[mt][2], a[mt], vl1[0], vl1[1]);
                mma16816h(acc[mt][3], a[mt], vh1[2], vh1[3]);
                mma16816h(acc[mt][3], a[mt], vl1[2], vl1[3]);
            }
        }
    }

    const int g = lane >> 2, tg = lane & 3;
    #pragma unroll
    for (int mt = 0; mt < 2; mt++) {
        #pragma unroll
        for (int nt = 0; nt < 4; nt++) {
            const int col = wn + nt * 8 + tg * 2;
            #pragma unroll
            for (int hh = 0; hh < 2; hh++) {
                const int row = q0 + wm + mt * 16 + g + hh * 8;
                if (row < T_) {
                    __half2 h2;
                    h2.x = __float2half(acc[mt][nt][hh * 2]);
                    h2.y = __float2half(acc[mt][nt][hh * 2 + 1]);
                    size_t go = ((size_t)(b * T_ + row)) * D_ + h * 64 + col;
                    *(__half2*)(wa16 + go) = h2;
                }
            }
        }
    }
}

// ---------------- host launch ----------------
extern "C" void kernel_launch(void* const* d_in, const int* in_sizes, int n_in,
                              void* d_out, int out_size) {
    const float* x      = (const float*)d_in[0];
    const float* ln1_w  = (const float*)d_in[1];
    const float* ln1_b  = (const float*)d_in[2];
    const float* qkv_w  = (const float*)d_in[3];
    const float* qkv_b  = (const float*)d_in[4];
    const float* proj_w = (const float*)d_in[5];
    const float* proj_b = (const float*)d_in[6];
    const float* ln2_w  = (const float*)d_in[7];
    const float* ln2_b  = (const float*)d_in[8];
    const float* fc1_w  = (const float*)d_in[9];
    const float* fc1_b  = (const float*)d_in[10];
    const float* fc2_w  = (const float*)d_in[11];
    const float* fc2_b  = (const float*)d_in[12];
    float* out = (float*)d_out;

    __half *y16, *qkh, *qkl, *dp16, *wa16, *h16, *ph;
    __half *wqh, *wql, *wph, *wpl, *w1hh, *w1ll, *w2hh, *w2ll;
    float *x1b;
    cudaGetSymbolAddress((void**)&y16,  g_y16);
    cudaGetSymbolAddress((void**)&qkh,  g_qkv_hi);
    cudaGetSymbolAddress((void**)&qkl,  g_qkv_lo);
    cudaGetSymbolAddress((void**)&dp16, g_dp16);
    cudaGetSymbolAddress((void**)&ph,   g_p);
    cudaGetSymbolAddress((void**)&wa16, g_wa16);
    cudaGetSymbolAddress((void**)&x1b,  g_x1);
    cudaGetSymbolAddress((void**)&h16,  g_h16);
    cudaGetSymbolAddress((void**)&wqh,  g_wq_hi);
    cudaGetSymbolAddress((void**)&wql,  g_wq_lo);
    cudaGetSymbolAddress((void**)&wph,  g_wp_hi);
    cudaGetSymbolAddress((void**)&wpl,  g_wp_lo);
    cudaGetSymbolAddress((void**)&w1hh, g_w1_hi);
    cudaGetSymbolAddress((void**)&w1ll, g_w1_lo);
    cudaGetSymbolAddress((void**)&w2hh, g_w2_hi);
    cudaGetSymbolAddress((void**)&w2ll, g_w2_lo);

    const int SMEM_H = 3 * (int)STGH;      // 73728
    const int SMEM_S = 2 * (int)STG;       // 81920
    const int SMEM_W = 3 * (int)STGW;      // 58368
    cudaFuncSetAttribute(gemm_hs<0, false, 2>, cudaFuncAttributeMaxDynamicSharedMemorySize, SMEM_H);
    cudaFuncSetAttribute(gemm_hs<0, true,  0>, cudaFuncAttributeMaxDynamicSharedMemorySize, SMEM_H);
    cudaFuncSetAttribute(gemm_hs<1, false, 1>, cudaFuncAttributeMaxDynamicSharedMemorySize, SMEM_H);
    cudaFuncSetAttribute(scores_mma,  cudaFuncAttributeMaxDynamicSharedMemorySize, SMEM_S);
    cudaFuncSetAttribute(wa_mma,      cudaFuncAttributeMaxDynamicSharedMemorySize, SMEM_W);

    const int MT = (BT + 127) / 128;  // 145

    wconv_h_kernel<<<dim3(2304 / 32, 768 / 32),  dim3(32, 8)>>>(qkv_w,  wqh,  wql,  768,  2304);
    wconv_h_kernel<<<dim3(768 / 32,  768 / 32),  dim3(32, 8)>>>(proj_w, wph,  wpl,  768,  768);
    wconv_h_kernel<<<dim3(3072 / 32, 768 / 32),  dim3(32, 8)>>>(fc1_w,  w1hh, w1ll, 768,  3072);
    wconv_h_kernel<<<dim3(768 / 32,  3072 / 32), dim3(32, 8)>>>(fc2_w,  w2hh, w2ll, 3072, 768);

    // 1) LN1 -> fp16 single
    ln_fp16_kernel<<<BT, 256>>>(x, ln1_w, ln1_b, y16);
    // 2) QKV projection (2-pass fp16) -> Q,K,V fp16 hi/lo split
    gemm_hs<0, false, 2><<<dim3(2304 / 128, MT), 256, SMEM_H>>>(
        y16, wqh, wql, qkv_b, nullptr, nullptr, qkh, qkl, BT, 2304, D_);
    // 3) scores (3-pass fp16) -> fp16 dp
    scores_mma<<<dim3(5, 5, B_ * NH), 256, SMEM_S>>>(qkh, qkl, dp16);
    // 4) softmax over heads (fp16 in) -> fp16 probs
    {
        long long total = (long long)B_ * (PTT / 4);
        int grid = (int)((total + 255) / 256);
        softmax_fp16<<<grid, 256>>>(dp16, ph);
    }
    // 5) wa = P @ V -> fp16 single
    wa_mma<<<dim3(5, B_ * NH), 256, SMEM_W>>>(ph, qkh, qkl, wa16);
    // 6) output projection + residual (2-pass fp16) -> fp32 x1
    gemm_hs<0, true, 0><<<dim3(D_ / 128, MT), 256, SMEM_H>>>(
        wa16, wph, wpl, proj_b, x, x1b, nullptr, nullptr, BT, D_, D_);
    // 7) LN2 -> fp16 single
    ln_fp16_kernel<<<BT, 256>>>(x1b, ln2_w, ln2_b, y16);
    // 8) fc1 + exact GELU (2-pass fp16) -> fp16 hidden
    gemm_hs<1, false, 1><<<dim3(H_ / 128, MT), 256, SMEM_H>>>(
        y16, w1hh, w1ll, fc1_b, nullptr, nullptr, h16, nullptr, BT, H_, D_);
    // 9) fc2 + residual (2-pass fp16) -> output
    gemm_hs<0, true, 0><<<dim3(D_ / 128, MT), 256, SMEM_H>>>(
        h16, w2hh, w2ll, fc2_b, x1b, out, nullptr, nullptr, BT, D_, H_);
}